// round 3
// baseline (speedup 1.0000x reference)
#include <cuda_runtime.h>
#include <cuda_bf16.h>

#define BATCH 256
#define TM1   63
#define NI    128
#define NH    128
#define GB    2
#define NCTA  (BATCH/GB)
#define NTHR  256
#define PPITCH 129

// Scratch (device globals: allocation-free rule)
__device__ float g_P[BATCH*TM1*NI];        // P[b][t][o] = aW1_x . X[b,t] + ab1
__device__ float g_WhhT[NH*4*NH];          // [128][512]  WhhT[k][j] = Whh[j][k]
__device__ float g_aW1hcT[2*NH*NI];        // [256][128]  aW1hcT[k][i] = aW1[i][k]

__device__ __forceinline__ float warp_sum(float v){
    v += __shfl_xor_sync(0xffffffffu, v, 16);
    v += __shfl_xor_sync(0xffffffffu, v, 8);
    v += __shfl_xor_sync(0xffffffffu, v, 4);
    v += __shfl_xor_sync(0xffffffffu, v, 2);
    v += __shfl_xor_sync(0xffffffffu, v, 1);
    return v;
}

__device__ __forceinline__ float ftanh(float x){
    float ax = fabsf(x);
    float e  = __expf(-2.0f*ax);
    float t  = __fdividef(1.0f - e, 1.0f + e);
    return (x < 0.0f) ? -t : t;
}
__device__ __forceinline__ float fsig(float x){
    return __fdividef(1.0f, 1.0f + __expf(-x));
}

#define BAR_A() asm volatile("bar.sync 1, 128;" ::: "memory")

// ---------------- prep: weight transposes ----------------
__global__ void prep_kernel(const float* __restrict__ aW1, const float* __restrict__ Whh){
    int tid = blockIdx.x*blockDim.x + threadIdx.x;
    int stride = gridDim.x*blockDim.x;
    for (int idx = tid; idx < 128*512; idx += stride){
        int k = idx >> 9, j = idx & 511;
        g_WhhT[idx] = Whh[j*128 + k];
    }
    for (int idx = tid; idx < 256*128; idx += stride){
        int k = idx >> 7, i = idx & 127;
        g_aW1hcT[idx] = aW1[i*384 + k];
    }
}

// ---------------- P precompute ----------------
__global__ void p_kernel(const float* __restrict__ X, const float* __restrict__ aW1,
                         const float* __restrict__ ab1){
    extern __shared__ char sraw[];
    float* Xs   = (float*)sraw;        // 8192 floats
    float* WT   = Xs + 8192;           // 128*129
    float* ab1s = WT + 128*129;        // 128
    int b = blockIdx.x, tid = threadIdx.x;

    for (int idx = tid; idx < 8192; idx += NTHR)
        Xs[idx] = (idx < TM1*NI) ? X[b*TM1*NI + idx] : 0.0f;
    for (int idx = tid; idx < 128*128; idx += NTHR){
        int o = idx >> 7, k = idx & 127;
        WT[k*129 + o] = aW1[o*384 + 256 + k];
    }
    if (tid < 128) ab1s[tid] = ab1[tid];
    __syncthreads();

    int o = tid & 127, half = tid >> 7;
    for (int tb = 0; tb < 8; tb++){
        int tbase = half*32 + tb*4;
        float bv = ab1s[o];
        float a0 = bv, a1 = bv, a2 = bv, a3 = bv;
        #pragma unroll 4
        for (int k = 0; k < 128; k++){
            float w = WT[k*129 + o];
            a0 = fmaf(Xs[(tbase+0)*128+k], w, a0);
            a1 = fmaf(Xs[(tbase+1)*128+k], w, a1);
            a2 = fmaf(Xs[(tbase+2)*128+k], w, a2);
            a3 = fmaf(Xs[(tbase+3)*128+k], w, a3);
        }
        if (tbase+0 < TM1) g_P[b*TM1*NI + (tbase+0)*128 + o] = a0;
        if (tbase+1 < TM1) g_P[b*TM1*NI + (tbase+1)*128 + o] = a1;
        if (tbase+2 < TM1) g_P[b*TM1*NI + (tbase+2)*128 + o] = a2;
        if (tbase+3 < TM1) g_P[b*TM1*NI + (tbase+3)*128 + o] = a3;
    }
}

// ---------------- main persistent recurrence (warp-specialized) ----------------
struct __align__(16) SmemMain {
    float hc[2*NH][GB];       // float2-accessed: [k] -> (g0,g1); k<128: h, k>=128: c
    float Xs[GB][TM1][NI];    // 64512 B
    float qs[GB][NI];
    float ctx[GB][NI];
    float gatesH[GB][4*NH];   // float4-stored
    float aw2[NI];
    float wo[2*NI];
    float wih[4*NH];
    float bsum[4*NH];
    float sc[GB][64];
    float be[GB][64];
    float Ys[GB][TM1+1];
    float wfc[132];           // [0..127]=Wfc[1..128], [128]=Wfc[0]
    float ssum[GB];
    float yup[GB];
    float Ps[GB][TM1*PPITCH]; // pitch 129, scalar access, conflict-free
};

__global__ void __launch_bounds__(NTHR, 1) main_kernel(
    const float* __restrict__ X, const float* __restrict__ Y,
    const float* __restrict__ aW2,
    const float* __restrict__ Wih, const float* __restrict__ bih, const float* __restrict__ bhh,
    const float* __restrict__ Wfc, const float* __restrict__ bfc,
    const float* __restrict__ Wo,  const float* __restrict__ bo,
    float* __restrict__ out)
{
    extern __shared__ char smraw[];
    SmemMain* sm = (SmemMain*)smraw;
    int tid = threadIdx.x;
    int b0  = blockIdx.x * GB;
    int w = tid >> 5, lane = tid & 31;

    // ---- stage everything ----
    for (int idx = tid; idx < GB*TM1*NI; idx += NTHR){
        int g = idx / (TM1*NI), r = idx % (TM1*NI);
        int tt = r >> 7, i = r & 127;
        sm->Xs[g][tt][i]          = X[b0*TM1*NI + idx];
        sm->Ps[g][tt*PPITCH + i]  = g_P[b0*TM1*NI + idx];
    }
    for (int idx = tid; idx < 4*NH; idx += NTHR){
        sm->wih[idx]  = Wih[idx];
        sm->bsum[idx] = bih[idx] + bhh[idx];
    }
    for (int idx = tid; idx < GB*TM1; idx += NTHR){
        int g = idx / TM1, tt = idx % TM1;
        sm->Ys[g][tt] = Y[(b0+g)*TM1 + tt];
    }
    if (tid < NI)   sm->aw2[tid] = aW2[tid];
    if (tid < 128)  sm->wfc[tid] = Wfc[tid+1];
    if (tid == 128) sm->wfc[128] = Wfc[0];
    if (tid < 2*NI) sm->wo[tid]  = Wo[tid];
    for (int idx = tid; idx < 2*NH*GB; idx += NTHR) ((float*)sm->hc)[idx] = 0.0f;
    __syncthreads();

    for (int t = 0; t < TM1; t++){
        if (tid < 128){
            // ======== G-group (warps 0-3): gates GEMV, streams WhhT (256KB) ========
            const float4* W4  = (const float4*)g_WhhT;   // row k: 128 float4
            const float2* hcp = (const float2*)sm->hc;
            float a0x=0.f,a0y=0.f,a0z=0.f,a0w=0.f;       // g=0, j=4*tid..+3
            float a1x=0.f,a1y=0.f,a1z=0.f,a1w=0.f;       // g=1
            #pragma unroll 8
            for (int k = 0; k < NH; k++){
                float4 wv = W4[k*128 + tid];
                float2 h2 = hcp[k];
                a0x = fmaf(wv.x,h2.x,a0x); a0y = fmaf(wv.y,h2.x,a0y);
                a0z = fmaf(wv.z,h2.x,a0z); a0w = fmaf(wv.w,h2.x,a0w);
                a1x = fmaf(wv.x,h2.y,a1x); a1y = fmaf(wv.y,h2.y,a1y);
                a1z = fmaf(wv.z,h2.y,a1z); a1w = fmaf(wv.w,h2.y,a1w);
            }
            ((float4*)sm->gatesH[0])[tid] = make_float4(a0x,a0y,a0z,a0w);
            ((float4*)sm->gatesH[1])[tid] = make_float4(a1x,a1y,a1z,a1w);
        } else {
            // ======== A-group (warps 4-7): q GEMV + attention chain ========
            int a  = tid - 128;
            int aw = a >> 5;
            // q[g][i] = sum_k aW1hcT[k][i] * hc[k][g]
            {
                const float2* hcp = (const float2*)sm->hc;
                float q0 = 0.f, q1 = 0.f;
                #pragma unroll 8
                for (int k = 0; k < 2*NH; k++){
                    float wv = g_aW1hcT[k*128 + a];
                    float2 h2 = hcp[k];
                    q0 = fmaf(wv, h2.x, q0);
                    q1 = fmaf(wv, h2.y, q1);
                }
                sm->qs[0][a] = q0;
                sm->qs[1][a] = q1;
            }
            BAR_A();
            // scores: one thread per (g,tt); a=63,127 idle
            {
                int g  = a >> 6;
                int tt = a & 63;
                if (tt < TM1){
                    const float* Prow = &sm->Ps[g][tt*PPITCH];
                    const float* qrow = sm->qs[g];
                    float acc = 0.f;
                    #pragma unroll 8
                    for (int i = 0; i < NI; i++)
                        acc = fmaf(sm->aw2[i], ftanh(Prow[i] + qrow[i]), acc);
                    sm->sc[g][tt] = acc;
                }
            }
            BAR_A();
            // softmax: warps 4 (g=0) and 6 (g=1)
            if ((aw & 1) == 0){
                int g = aw >> 1;
                float s0 = sm->sc[g][lane];
                float s1 = (lane < 31) ? sm->sc[g][32+lane] : -3.0e38f;
                float m = fmaxf(s0, s1);
                #pragma unroll
                for (int off = 16; off > 0; off >>= 1)
                    m = fmaxf(m, __shfl_xor_sync(0xffffffffu, m, off));
                float e0 = __expf(s0 - m);
                float e1 = (lane < 31) ? __expf(s1 - m) : 0.0f;
                float ssv = warp_sum(e0 + e1);
                sm->be[g][lane] = e0;
                if (lane < 31) sm->be[g][32+lane] = e1;
                if (lane == 0) sm->ssum[g] = ssv;
            }
            BAR_A();
            // context: thread a owns column i=a for both g
            {
                float c0 = 0.f, c1 = 0.f;
                #pragma unroll
                for (int tt = 0; tt < TM1; tt++){
                    float b0v = sm->be[0][tt], b1v = sm->be[1][tt];
                    c0 = fmaf(b0v, sm->Xs[0][tt][a], c0);
                    c1 = fmaf(b1v, sm->Xs[1][tt][a], c1);
                }
                sm->ctx[0][a] = c0 * __fdividef(1.0f, sm->ssum[0]);
                sm->ctx[1][a] = c1 * __fdividef(1.0f, sm->ssum[1]);
            }
            BAR_A();
            // y_update: warps 4 (g=0) and 6 (g=1)
            if ((aw & 1) == 0){
                int g = aw >> 1;
                float acc = 0.f;
                #pragma unroll
                for (int r = 0; r < 4; r++){
                    int i = lane*4 + r;
                    acc = fmaf(sm->wfc[i], sm->ctx[g][i], acc);
                }
                acc = warp_sum(acc);
                if (lane == 0){
                    float yt = sm->Ys[g][t];
                    sm->yup[g] = bfc[0] + sm->wfc[128]*yt + acc;
                }
            }
        }
        __syncthreads();
        // ======== LSTM cell: all 256 threads, one (g,jj) each ========
        {
            int g = tid >> 7, jj = tid & 127;
            float yu = sm->yup[g];
            float gi = sm->gatesH[g][jj]      + yu*sm->wih[jj]      + sm->bsum[jj];
            float gf = sm->gatesH[g][NH+jj]   + yu*sm->wih[NH+jj]   + sm->bsum[NH+jj];
            float gg = sm->gatesH[g][2*NH+jj] + yu*sm->wih[2*NH+jj] + sm->bsum[2*NH+jj];
            float go = sm->gatesH[g][3*NH+jj] + yu*sm->wih[3*NH+jj] + sm->bsum[3*NH+jj];
            float co = sm->hc[NH+jj][g];
            float cn = fsig(gf)*co + fsig(gi)*ftanh(gg);
            float hn = fsig(go)*ftanh(cn);
            sm->hc[jj][g]    = hn;
            sm->hc[NH+jj][g] = cn;
        }
        __syncthreads();
    }

    // ---- output: y[b] = bo + Wo[0:128].h + Wo[128:256].ctx  (warps 0 and 4)
    if (w == 0 || w == 4){
        int g = (w == 4);
        float acc = 0.0f;
        #pragma unroll
        for (int r = 0; r < 4; r++){
            int i = lane*4 + r;
            acc += sm->wo[i]*sm->hc[i][g] + sm->wo[NI+i]*sm->ctx[g][i];
        }
        acc = warp_sum(acc);
        if (lane == 0) out[b0 + g] = acc + bo[0];
    }
}

extern "C" void kernel_launch(void* const* d_in, const int* in_sizes, int n_in,
                              void* d_out, int out_size) {
    const float* X   = (const float*)d_in[0];
    const float* Y   = (const float*)d_in[1];
    const float* aW1 = (const float*)d_in[2];
    const float* ab1 = (const float*)d_in[3];
    const float* aW2 = (const float*)d_in[4];
    // d_in[5] = ab2: constant softmax shift, mathematically irrelevant
    const float* Wih = (const float*)d_in[6];
    const float* Whh = (const float*)d_in[7];
    const float* bih = (const float*)d_in[8];
    const float* bhh = (const float*)d_in[9];
    const float* Wfc = (const float*)d_in[10];
    const float* bfc = (const float*)d_in[11];
    const float* Wo  = (const float*)d_in[12];
    const float* bo  = (const float*)d_in[13];
    float* out = (float*)d_out;

    size_t p_smem = (size_t)(8192 + 128*129 + 128) * sizeof(float);
    size_t m_smem = sizeof(SmemMain);
    cudaFuncSetAttribute(p_kernel,    cudaFuncAttributeMaxDynamicSharedMemorySize, (int)p_smem);
    cudaFuncSetAttribute(main_kernel, cudaFuncAttributeMaxDynamicSharedMemorySize, (int)m_smem);

    prep_kernel<<<64, 256>>>(aW1, Whh);
    p_kernel<<<BATCH, NTHR, p_smem>>>(X, aW1, ab1);
    main_kernel<<<NCTA, NTHR, m_smem>>>(X, Y, aW2, Wih, bih, bhh, Wfc, bfc, Wo, bo, out);
}

// round 4
// speedup vs baseline: 1.1557x; 1.1557x over previous
#include <cuda_runtime.h>
#include <cuda_bf16.h>

#define BATCH 256
#define TM1   63
#define NI    128
#define NH    128
#define GB    2
#define NCTA  (BATCH/GB)
#define NTHR  256

// Scratch (device globals: allocation-free rule)
__device__ float g_P[BATCH*TM1*NI];        // P[b][t][o] = aW1_x . X[b,t] + ab1
__device__ float g_WhhT[NH*4*NH];          // [128][512]  WhhT[k][j] = Whh[j][k]
__device__ float g_aW1hcT[2*NH*NI];        // [256][128]  aW1hcT[k][i] = aW1[i][k]

__device__ __forceinline__ float warp_sum(float v){
    v += __shfl_xor_sync(0xffffffffu, v, 16);
    v += __shfl_xor_sync(0xffffffffu, v, 8);
    v += __shfl_xor_sync(0xffffffffu, v, 4);
    v += __shfl_xor_sync(0xffffffffu, v, 2);
    v += __shfl_xor_sync(0xffffffffu, v, 1);
    return v;
}

__device__ __forceinline__ float ex2_approx(float x){
    float r;
    asm("ex2.approx.f32 %0, %1;" : "=f"(r) : "f"(x));
    return r;
}

// FFMA-only reciprocal for d in [1,2]: quadratic guess + 3 Newton steps, 0 MUFU
__device__ __forceinline__ float rcp12(float d){
    float r = fmaf(d, 0.333333333f, -1.5f);
    r = fmaf(d, r, 2.166666667f);            // ~5e-2 rel err
    float e1 = fmaf(-d, r, 1.0f); r = fmaf(r, e1, r);
    float e2 = fmaf(-d, r, 1.0f); r = fmaf(r, e2, r);
    float e3 = fmaf(-d, r, 1.0f); r = fmaf(r, e3, r);
    return r;
}

// tanh with 1 MUFU (EX2) + FFMA Newton reciprocal; rel err ~1e-7
__device__ __forceinline__ float ftanh(float x){
    float ax = fabsf(x);
    float e  = ex2_approx(ax * -2.885390082f);   // e^{-2ax}
    float r  = rcp12(1.0f + e);                  // 1/(1+e)
    float t  = fmaf(-e, r, r);                   // (1-e)/(1+e)
    return (x < 0.0f) ? -t : t;
}
// sigmoid = 0.5 + 0.5*tanh(x/2): 1 MUFU
__device__ __forceinline__ float fsig(float x){
    return fmaf(0.5f, ftanh(0.5f * x), 0.5f);
}

// ---------------- prep: weight transposes ----------------
__global__ void prep_kernel(const float* __restrict__ aW1, const float* __restrict__ Whh){
    int tid = blockIdx.x*blockDim.x + threadIdx.x;
    int stride = gridDim.x*blockDim.x;
    for (int idx = tid; idx < 128*512; idx += stride){
        int k = idx >> 9, j = idx & 511;
        g_WhhT[idx] = Whh[j*128 + k];
    }
    for (int idx = tid; idx < 256*128; idx += stride){
        int k = idx >> 7, i = idx & 127;
        g_aW1hcT[idx] = aW1[i*384 + k];
    }
}

// ---------------- P precompute ----------------
__global__ void p_kernel(const float* __restrict__ X, const float* __restrict__ aW1,
                         const float* __restrict__ ab1){
    extern __shared__ char sraw[];
    float* Xs   = (float*)sraw;        // 8192 floats
    float* WT   = Xs + 8192;           // 128*129
    float* ab1s = WT + 128*129;        // 128
    int b = blockIdx.x, tid = threadIdx.x;

    for (int idx = tid; idx < 8192; idx += NTHR)
        Xs[idx] = (idx < TM1*NI) ? X[b*TM1*NI + idx] : 0.0f;
    for (int idx = tid; idx < 128*128; idx += NTHR){
        int o = idx >> 7, k = idx & 127;
        WT[k*129 + o] = aW1[o*384 + 256 + k];
    }
    if (tid < 128) ab1s[tid] = ab1[tid];
    __syncthreads();

    int o = tid & 127, half = tid >> 7;
    for (int tb = 0; tb < 8; tb++){
        int tbase = half*32 + tb*4;
        float bv = ab1s[o];
        float a0 = bv, a1 = bv, a2 = bv, a3 = bv;
        #pragma unroll 4
        for (int k = 0; k < 128; k++){
            float w = WT[k*129 + o];
            a0 = fmaf(Xs[(tbase+0)*128+k], w, a0);
            a1 = fmaf(Xs[(tbase+1)*128+k], w, a1);
            a2 = fmaf(Xs[(tbase+2)*128+k], w, a2);
            a3 = fmaf(Xs[(tbase+3)*128+k], w, a3);
        }
        if (tbase+0 < TM1) g_P[b*TM1*NI + (tbase+0)*128 + o] = a0;
        if (tbase+1 < TM1) g_P[b*TM1*NI + (tbase+1)*128 + o] = a1;
        if (tbase+2 < TM1) g_P[b*TM1*NI + (tbase+2)*128 + o] = a2;
        if (tbase+3 < TM1) g_P[b*TM1*NI + (tbase+3)*128 + o] = a3;
    }
}

// ---------------- main persistent recurrence ----------------
struct __align__(16) SmemMain {
    float Xs[GB][TM1][NI];
    float Ps[GB][TM1][NI];
    float qs[GB][NI];
    float ctx[GB][NI];
    float aw2[NI];
    float wfc[132];           // [0..127] = Wfc[1..128], [128] = Wfc[0]
    float wo[2*NI];
    float hc[2*NH][GB];       // [k][g], k<128 -> h, k>=128 -> c
    float qpart[4][GB][NI];
    float gatesH[GB][4*NH];
    float sc[GB][64];
    float be[GB][64];
    float wih[4*NH];
    float bsum[4*NH];
    float Ys[GB][TM1+1];
    float ssum[GB];
    float yup[GB];
};

__global__ void __launch_bounds__(NTHR, 1) main_kernel(
    const float* __restrict__ X, const float* __restrict__ Y,
    const float* __restrict__ aW2,
    const float* __restrict__ Wih, const float* __restrict__ bih, const float* __restrict__ bhh,
    const float* __restrict__ Wfc, const float* __restrict__ bfc,
    const float* __restrict__ Wo,  const float* __restrict__ bo,
    float* __restrict__ out)
{
    extern __shared__ char smraw[];
    SmemMain* sm = (SmemMain*)smraw;
    int tid = threadIdx.x;
    int b0  = blockIdx.x * GB;
    int w = tid >> 5, lane = tid & 31;

    // stage X, P, small weights
    for (int idx = tid; idx < GB*TM1*NI; idx += NTHR){
        ((float*)sm->Xs)[idx] = X[b0*TM1*NI + idx];
        ((float*)sm->Ps)[idx] = g_P[b0*TM1*NI + idx];
    }
    for (int idx = tid; idx < 4*NH; idx += NTHR){
        sm->wih[idx]  = Wih[idx];
        sm->bsum[idx] = bih[idx] + bhh[idx];
    }
    for (int idx = tid; idx < GB*TM1; idx += NTHR){
        int g = idx / TM1, tt = idx % TM1;
        sm->Ys[g][tt] = Y[(b0+g)*TM1 + tt];
    }
    if (tid < NI)  sm->aw2[tid] = aW2[tid];
    if (tid < 128) sm->wfc[tid] = Wfc[tid+1];
    if (tid == 128) sm->wfc[128] = Wfc[0];
    if (tid < 2*NI) sm->wo[tid] = Wo[tid];
    for (int idx = tid; idx < 2*NH*GB; idx += NTHR) ((float*)sm->hc)[idx] = 0.0f;
    __syncthreads();

    for (int t = 0; t < TM1; t++){
        // ---- phase 1a: gatesH[g][j] = Whh[j,:] . h_g  (thread owns j=2*tid, 2*tid+1)
        {
            const float2* W2  = (const float2*)g_WhhT;     // row k: 256 float2
            const float2* hcp = (const float2*)sm->hc;     // (h_g0, h_g1) per k
            float a00=0.f, a01=0.f, a10=0.f, a11=0.f;
            #pragma unroll 16
            for (int k = 0; k < NH; k++){
                float2 wv = W2[k*256 + tid];
                float2 h2 = hcp[k];
                a00 = fmaf(wv.x, h2.x, a00); a01 = fmaf(wv.y, h2.x, a01);
                a10 = fmaf(wv.x, h2.y, a10); a11 = fmaf(wv.y, h2.y, a11);
            }
            sm->gatesH[0][2*tid]   = a00; sm->gatesH[0][2*tid+1] = a01;
            sm->gatesH[1][2*tid]   = a10; sm->gatesH[1][2*tid+1] = a11;
        }
        // ---- phase 1b: q partial dots (quarter of k-range per thread group)
        {
            int qt = tid >> 6, il = tid & 63;
            const float2* W2  = (const float2*)g_aW1hcT;   // row k: 64 float2
            const float2* hcp = (const float2*)sm->hc;
            float a00=0.f, a01=0.f, a10=0.f, a11=0.f;
            #pragma unroll 16
            for (int kk = 0; kk < 64; kk++){
                int k = qt*64 + kk;
                float2 wv = W2[k*64 + il];
                float2 h2 = hcp[k];
                a00 = fmaf(wv.x, h2.x, a00); a01 = fmaf(wv.y, h2.x, a01);
                a10 = fmaf(wv.x, h2.y, a10); a11 = fmaf(wv.y, h2.y, a11);
            }
            sm->qpart[qt][0][2*il] = a00; sm->qpart[qt][0][2*il+1] = a01;
            sm->qpart[qt][1][2*il] = a10; sm->qpart[qt][1][2*il+1] = a11;
        }
        __syncthreads();
        // combine q quarters
        {
            int g = tid >> 7, i = tid & 127;
            sm->qs[g][i] = sm->qpart[0][g][i] + sm->qpart[1][g][i]
                         + sm->qpart[2][g][i] + sm->qpart[3][g][i];
        }
        __syncthreads();
        // ---- scores: warps 0-3 -> g=0, warps 4-7 -> g=1
        {
            int g = w >> 2, gw = w & 3;
            float4 a2 = ((const float4*)sm->aw2)[lane];
            float4 qv = ((const float4*)sm->qs[g])[lane];
            for (int tt = gw; tt < TM1; tt += 4){
                float4 p = ((const float4*)sm->Ps[g][tt])[lane];
                float sv = a2.x*ftanh(p.x+qv.x) + a2.y*ftanh(p.y+qv.y)
                         + a2.z*ftanh(p.z+qv.z) + a2.w*ftanh(p.w+qv.w);
                sv = warp_sum(sv);
                if (lane == 0) sm->sc[g][tt] = sv;
            }
        }
        __syncthreads();
        // ---- softmax (warps 0 and 4), keep unnormalized exp + sum
        if ((w & 3) == 0){
            int g = w >> 2;
            float s0 = sm->sc[g][lane];
            float s1 = (lane < 31) ? sm->sc[g][32+lane] : -3.0e38f;
            float m = fmaxf(s0, s1);
            #pragma unroll
            for (int off = 16; off > 0; off >>= 1)
                m = fmaxf(m, __shfl_xor_sync(0xffffffffu, m, off));
            float e0 = __expf(s0 - m);
            float e1 = (lane < 31) ? __expf(s1 - m) : 0.0f;
            float ssv = warp_sum(e0 + e1);
            sm->be[g][lane] = e0;
            if (lane < 31) sm->be[g][32+lane] = e1;
            if (lane == 0) sm->ssum[g] = ssv;
        }
        __syncthreads();
        // ---- context
        {
            int g = tid >> 7, i = tid & 127;
            float acc = 0.0f;
            #pragma unroll
            for (int tt = 0; tt < TM1; tt++)
                acc = fmaf(sm->be[g][tt], sm->Xs[g][tt][i], acc);
            sm->ctx[g][i] = acc * __fdividef(1.0f, sm->ssum[g]);
        }
        __syncthreads();
        // ---- y_update (warps 0 and 4)
        if ((w & 3) == 0){
            int g = w >> 2;
            float4 wf = ((const float4*)sm->wfc)[lane];
            float4 cv = ((const float4*)sm->ctx[g])[lane];
            float acc = wf.x*cv.x + wf.y*cv.y + wf.z*cv.z + wf.w*cv.w;
            acc = warp_sum(acc);
            if (lane == 0){
                float yt = sm->Ys[g][t];
                sm->yup[g] = bfc[0] + sm->wfc[128]*yt + acc;
            }
        }
        __syncthreads();
        // ---- LSTM cell
        {
            int g = tid >> 7, jj = tid & 127;
            float yu = sm->yup[g];
            float gi = sm->gatesH[g][jj]      + yu*sm->wih[jj]      + sm->bsum[jj];
            float gf = sm->gatesH[g][NH+jj]   + yu*sm->wih[NH+jj]   + sm->bsum[NH+jj];
            float gg = sm->gatesH[g][2*NH+jj] + yu*sm->wih[2*NH+jj] + sm->bsum[2*NH+jj];
            float go = sm->gatesH[g][3*NH+jj] + yu*sm->wih[3*NH+jj] + sm->bsum[3*NH+jj];
            float co = sm->hc[NH+jj][g];
            float cn = fsig(gf)*co + fsig(gi)*ftanh(gg);
            float hn = fsig(go)*ftanh(cn);
            sm->hc[jj][g]    = hn;
            sm->hc[NH+jj][g] = cn;
        }
        __syncthreads();
    }

    // ---- output: y[b] = bo + Wo[0:128].h + Wo[128:256].ctx
    if ((w & 3) == 0){
        int g = w >> 2;
        float acc = 0.0f;
        #pragma unroll
        for (int r = 0; r < 4; r++){
            int i = lane*4 + r;
            acc += sm->wo[i]*sm->hc[i][g] + sm->wo[NI+i]*sm->ctx[g][i];
        }
        acc = warp_sum(acc);
        if (lane == 0) out[b0 + g] = acc + bo[0];
    }
}

extern "C" void kernel_launch(void* const* d_in, const int* in_sizes, int n_in,
                              void* d_out, int out_size) {
    const float* X   = (const float*)d_in[0];
    const float* Y   = (const float*)d_in[1];
    const float* aW1 = (const float*)d_in[2];
    const float* ab1 = (const float*)d_in[3];
    const float* aW2 = (const float*)d_in[4];
    // d_in[5] = ab2: constant softmax shift, mathematically irrelevant
    const float* Wih = (const float*)d_in[6];
    const float* Whh = (const float*)d_in[7];
    const float* bih = (const float*)d_in[8];
    const float* bhh = (const float*)d_in[9];
    const float* Wfc = (const float*)d_in[10];
    const float* bfc = (const float*)d_in[11];
    const float* Wo  = (const float*)d_in[12];
    const float* bo  = (const float*)d_in[13];
    float* out = (float*)d_out;

    size_t p_smem = (size_t)(8192 + 128*129 + 128) * sizeof(float);
    size_t m_smem = sizeof(SmemMain);
    cudaFuncSetAttribute(p_kernel,    cudaFuncAttributeMaxDynamicSharedMemorySize, (int)p_smem);
    cudaFuncSetAttribute(main_kernel, cudaFuncAttributeMaxDynamicSharedMemorySize, (int)m_smem);

    prep_kernel<<<64, 256>>>(aW1, Whh);
    p_kernel<<<BATCH, NTHR, p_smem>>>(X, aW1, ab1);
    main_kernel<<<NCTA, NTHR, m_smem>>>(X, Y, aW2, Wih, bih, bhh, Wfc, bfc, Wo, bo, out);
}

// round 6
// speedup vs baseline: 1.4665x; 1.2690x over previous
#include <cuda_runtime.h>
#include <cuda_bf16.h>

#define BATCH 256
#define TM1   63
#define NI    128
#define NH    128
#define GB    2
#define NCTA  (BATCH/GB)
#define NTHR  256
#define PPITCH 129

// Scratch (device globals: allocation-free rule)
__device__ float g_P[BATCH*TM1*NI];        // P[b][t][o] = aW1_x . X[b,t] + ab1
__device__ float g_WhhT[NH*4*NH];          // [128][512]  WhhT[k][j] = Whh[j][k]
__device__ float g_aW1hcT[2*NH*NI];        // [256][128]  aW1hcT[k][i] = aW1[i][k]

__device__ __forceinline__ float warp_sum(float v){
    v += __shfl_xor_sync(0xffffffffu, v, 16);
    v += __shfl_xor_sync(0xffffffffu, v, 8);
    v += __shfl_xor_sync(0xffffffffu, v, 4);
    v += __shfl_xor_sync(0xffffffffu, v, 2);
    v += __shfl_xor_sync(0xffffffffu, v, 1);
    return v;
}

__device__ __forceinline__ float ex2_approx(float x){
    float r;
    asm("ex2.approx.f32 %0, %1;" : "=f"(r) : "f"(x));
    return r;
}

// tanh: 2 MUFU (EX2 + RCP via fast div), few FFMA. rel err ~1e-6
__device__ __forceinline__ float ftanh(float x){
    float ax = fabsf(x);
    float e  = ex2_approx(ax * -2.885390082f);   // e^{-2ax}
    float t  = __fdividef(1.0f - e, 1.0f + e);
    return copysignf(t, x);
}
__device__ __forceinline__ float fsig(float x){
    return __fdividef(1.0f, 1.0f + ex2_approx(x * -1.442695041f));
}

// ---------------- prep: weight transposes ----------------
__global__ void prep_kernel(const float* __restrict__ aW1, const float* __restrict__ Whh){
    int tid = blockIdx.x*blockDim.x + threadIdx.x;
    int stride = gridDim.x*blockDim.x;
    for (int idx = tid; idx < 128*512; idx += stride){
        int k = idx >> 9, j = idx & 511;
        g_WhhT[idx] = Whh[j*128 + k];
    }
    for (int idx = tid; idx < 256*128; idx += stride){
        int k = idx >> 7, i = idx & 127;
        g_aW1hcT[idx] = aW1[i*384 + k];
    }
}

// ---------------- P precompute ----------------
__global__ void p_kernel(const float* __restrict__ X, const float* __restrict__ aW1,
                         const float* __restrict__ ab1){
    extern __shared__ char sraw[];
    float* Xs   = (float*)sraw;        // 8192 floats
    float* WT   = Xs + 8192;           // 128*129
    float* ab1s = WT + 128*129;        // 128
    int b = blockIdx.x, tid = threadIdx.x;

    for (int idx = tid; idx < 8192; idx += NTHR)
        Xs[idx] = (idx < TM1*NI) ? X[b*TM1*NI + idx] : 0.0f;
    for (int idx = tid; idx < 128*128; idx += NTHR){
        int o = idx >> 7, k = idx & 127;
        WT[k*129 + o] = aW1[o*384 + 256 + k];
    }
    if (tid < 128) ab1s[tid] = ab1[tid];
    __syncthreads();

    int o = tid & 127, half = tid >> 7;
    for (int tb = 0; tb < 8; tb++){
        int tbase = half*32 + tb*4;
        float bv = ab1s[o];
        float a0 = bv, a1 = bv, a2 = bv, a3 = bv;
        #pragma unroll 4
        for (int k = 0; k < 128; k++){
            float w = WT[k*129 + o];
            a0 = fmaf(Xs[(tbase+0)*128+k], w, a0);
            a1 = fmaf(Xs[(tbase+1)*128+k], w, a1);
            a2 = fmaf(Xs[(tbase+2)*128+k], w, a2);
            a3 = fmaf(Xs[(tbase+3)*128+k], w, a3);
        }
        if (tbase+0 < TM1) g_P[b*TM1*NI + (tbase+0)*128 + o] = a0;
        if (tbase+1 < TM1) g_P[b*TM1*NI + (tbase+1)*128 + o] = a1;
        if (tbase+2 < TM1) g_P[b*TM1*NI + (tbase+2)*128 + o] = a2;
        if (tbase+3 < TM1) g_P[b*TM1*NI + (tbase+3)*128 + o] = a3;
    }
}

// ---------------- main persistent recurrence ----------------
struct __align__(16) SmemMain {
    float Xs[GB][TM1][NI];        // 64512 B
    float Ps[GB][TM1][PPITCH];    // pitch 129, scalar access
    float qpart[4][GB][NI];
    float qs[GB][NI];
    float ctx[GB][NI];
    float gatesH[GB][4*NH];
    float aw2[NI];
    float wfc[132];               // [0..127]=Wfc[1..128], [128]=Wfc[0]
    float wo[2*NI];
    float hc[2*NH][GB];           // [k][g]; k<128: h, k>=128: c
    float scpart[2][GB][64];
    float be[GB][64];
    float XW[GB][64];             // XW[g][tt] = wfc . X[g][tt][:]
    float wih[4*NH];
    float bsum[4*NH];
    float Ys[GB][TM1+1];
    float rinv[GB];
    float yup[GB];
};

__global__ void __launch_bounds__(NTHR, 1) main_kernel(
    const float* __restrict__ X, const float* __restrict__ Y,
    const float* __restrict__ aW2,
    const float* __restrict__ Wih, const float* __restrict__ bih, const float* __restrict__ bhh,
    const float* __restrict__ Wfc, const float* __restrict__ bfc,
    const float* __restrict__ Wo,  const float* __restrict__ bo,
    float* __restrict__ out)
{
    extern __shared__ char smraw[];
    SmemMain* sm = (SmemMain*)smraw;
    int tid = threadIdx.x;
    int b0  = blockIdx.x * GB;
    int w = tid >> 5, lane = tid & 31;

    // ---- stage ----
    for (int idx = tid; idx < GB*TM1*NI; idx += NTHR){
        int g = idx / (TM1*NI), r = idx % (TM1*NI);
        int tt = r >> 7, i = r & 127;
        sm->Xs[g][tt][i] = X[b0*TM1*NI + idx];
        sm->Ps[g][tt][i] = g_P[b0*TM1*NI + idx];
    }
    for (int idx = tid; idx < 4*NH; idx += NTHR){
        sm->wih[idx]  = Wih[idx];
        sm->bsum[idx] = bih[idx] + bhh[idx];
    }
    for (int idx = tid; idx < GB*TM1; idx += NTHR){
        int g = idx / TM1, tt = idx % TM1;
        sm->Ys[g][tt] = Y[(b0+g)*TM1 + tt];
    }
    if (tid < NI)   sm->aw2[tid] = aW2[tid];
    if (tid < 128)  sm->wfc[tid] = Wfc[tid+1];
    if (tid == 128) sm->wfc[128] = Wfc[0];
    if (tid < 2*NI) sm->wo[tid]  = Wo[tid];
    for (int idx = tid; idx < 2*NH*GB; idx += NTHR) ((float*)sm->hc)[idx] = 0.0f;
    __syncthreads();

    // ---- one-time: XW[g][tt] = sum_i wfc[i]*Xs[g][tt][i] ----
    if (tid < GB*64){
        int g = tid >> 6, tt = tid & 63;
        float acc = 0.0f;
        if (tt < TM1){
            #pragma unroll 8
            for (int i = 0; i < NI; i++)
                acc = fmaf(sm->wfc[i], sm->Xs[g][tt][i], acc);
        }
        sm->XW[g][tt] = acc;   // tt=63 -> 0
    }
    __syncthreads();

    const float bfc0 = bfc[0];

    for (int t = 0; t < TM1; t++){
        // ======== phase 1: gates GEMV + q partials ========
        {
            const float2* W2  = (const float2*)g_WhhT;     // row k: 256 float2
            const float2* hcp = (const float2*)sm->hc;
            float a00=0.f, a01=0.f, a10=0.f, a11=0.f;
            #pragma unroll 16
            for (int k = 0; k < NH; k++){
                float2 wv = W2[k*256 + tid];
                float2 h2 = hcp[k];
                a00 = fmaf(wv.x, h2.x, a00); a01 = fmaf(wv.y, h2.x, a01);
                a10 = fmaf(wv.x, h2.y, a10); a11 = fmaf(wv.y, h2.y, a11);
            }
            sm->gatesH[0][2*tid]   = a00; sm->gatesH[0][2*tid+1] = a01;
            sm->gatesH[1][2*tid]   = a10; sm->gatesH[1][2*tid+1] = a11;
        }
        {
            int qt = tid >> 6, il = tid & 63;
            const float2* W2  = (const float2*)g_aW1hcT;   // row k: 64 float2
            const float2* hcp = (const float2*)sm->hc;
            float a00=0.f, a01=0.f, a10=0.f, a11=0.f;
            #pragma unroll 16
            for (int kk = 0; kk < 64; kk++){
                int k = qt*64 + kk;
                float2 wv = W2[k*64 + il];
                float2 h2 = hcp[k];
                a00 = fmaf(wv.x, h2.x, a00); a01 = fmaf(wv.y, h2.x, a01);
                a10 = fmaf(wv.x, h2.y, a10); a11 = fmaf(wv.y, h2.y, a11);
            }
            sm->qpart[qt][0][2*il] = a00; sm->qpart[qt][0][2*il+1] = a01;
            sm->qpart[qt][1][2*il] = a10; sm->qpart[qt][1][2*il+1] = a11;
        }
        __syncthreads();
        // ======== phase 2: scores (thread = (g, half, tt)) ========
        {
            int g  = tid >> 7;
            int r  = tid & 127;
            int h  = r >> 6;
            int tt = r & 63;
            int ibase = h * 64;
            // warp-local q combine (each warp redundantly combines its own 64-i range)
            {
                int i2 = (ibase >> 1) + lane;       // float2 index within [g] row
                const float2* q0 = (const float2*)sm->qpart[0][g];
                const float2* q1 = (const float2*)sm->qpart[1][g];
                const float2* q2 = (const float2*)sm->qpart[2][g];
                const float2* q3 = (const float2*)sm->qpart[3][g];
                float2 a = q0[i2], b = q1[i2], c = q2[i2], d = q3[i2];
                ((float2*)sm->qs[g])[i2] = make_float2(a.x+b.x+c.x+d.x, a.y+b.y+c.y+d.y);
            }
            __syncwarp();
            float acc = 0.0f;
            if (tt < TM1){
                const float* Prow = &sm->Ps[g][tt][ibase];
                const float* qrow = &sm->qs[g][ibase];
                const float* arow = &sm->aw2[ibase];
                #pragma unroll 8
                for (int i = 0; i < 64; i++)
                    acc = fmaf(arow[i], ftanh(Prow[i] + qrow[i]), acc);
            }
            sm->scpart[h][g][tt] = acc;
        }
        __syncthreads();
        // ======== phase 3: softmax + y_update (warps 0 and 4) ========
        if (w == 0 || w == 4){
            int g = w >> 2;
            float s0 = sm->scpart[0][g][lane] + sm->scpart[1][g][lane];
            float s1 = (lane < 31) ? (sm->scpart[0][g][32+lane] + sm->scpart[1][g][32+lane])
                                   : -3.0e38f;
            float m = fmaxf(s0, s1);
            #pragma unroll
            for (int off = 16; off > 0; off >>= 1)
                m = fmaxf(m, __shfl_xor_sync(0xffffffffu, m, off));
            float e0 = ex2_approx((s0 - m) * 1.442695041f);
            float e1 = (lane < 31) ? ex2_approx((s1 - m) * 1.442695041f) : 0.0f;
            float sv = e0 + e1;
            float dv = e0 * sm->XW[g][lane] + e1 * sm->XW[g][32 + lane];
            #pragma unroll
            for (int off = 16; off > 0; off >>= 1){
                sv += __shfl_xor_sync(0xffffffffu, sv, off);
                dv += __shfl_xor_sync(0xffffffffu, dv, off);
            }
            sm->be[g][lane] = e0;
            if (lane < 31) sm->be[g][32+lane] = e1;
            if (lane == 0){
                float ri = __fdividef(1.0f, sv);
                sm->rinv[g] = ri;
                float yt = sm->Ys[g][t];
                sm->yup[g] = fmaf(dv, ri, fmaf(sm->wfc[128], yt, bfc0));
            }
        }
        __syncthreads();
        // ======== phase 4: context + LSTM cell (fused; independent outputs) ========
        {
            int g = tid >> 7, i = tid & 127;
            float acc = 0.0f;
            #pragma unroll
            for (int tt = 0; tt < TM1; tt++)
                acc = fmaf(sm->be[g][tt], sm->Xs[g][tt][i], acc);
            sm->ctx[g][i] = acc * sm->rinv[g];

            float yu = sm->yup[g];
            float gi = sm->gatesH[g][i]        + yu*sm->wih[i]        + sm->bsum[i];
            float gf = sm->gatesH[g][NH+i]     + yu*sm->wih[NH+i]     + sm->bsum[NH+i];
            float gg = sm->gatesH[g][2*NH+i]   + yu*sm->wih[2*NH+i]   + sm->bsum[2*NH+i];
            float go = sm->gatesH[g][3*NH+i]   + yu*sm->wih[3*NH+i]   + sm->bsum[3*NH+i];
            float co = sm->hc[NH+i][g];
            float cn = fsig(gf)*co + fsig(gi)*ftanh(gg);
            float hn = fsig(go)*ftanh(cn);
            sm->hc[i][g]    = hn;
            sm->hc[NH+i][g] = cn;
        }
        __syncthreads();
    }

    // ---- output: y[b] = bo + Wo[0:128].h + Wo[128:256].ctx ----
    if (w == 0 || w == 4){
        int g = w >> 2;
        float acc = 0.0f;
        #pragma unroll
        for (int r = 0; r < 4; r++){
            int i = lane*4 + r;
            acc += sm->wo[i]*sm->hc[i][g] + sm->wo[NI+i]*sm->ctx[g][i];
        }
        acc = warp_sum(acc);
        if (lane == 0) out[b0 + g] = acc + bo[0];
    }
}

extern "C" void kernel_launch(void* const* d_in, const int* in_sizes, int n_in,
                              void* d_out, int out_size) {
    const float* X   = (const float*)d_in[0];
    const float* Y   = (const float*)d_in[1];
    const float* aW1 = (const float*)d_in[2];
    const float* ab1 = (const float*)d_in[3];
    const float* aW2 = (const float*)d_in[4];
    // d_in[5] = ab2: constant softmax shift, mathematically irrelevant
    const float* Wih = (const float*)d_in[6];
    const float* Whh = (const float*)d_in[7];
    const float* bih = (const float*)d_in[8];
    const float* bhh = (const float*)d_in[9];
    const float* Wfc = (const float*)d_in[10];
    const float* bfc = (const float*)d_in[11];
    const float* Wo  = (const float*)d_in[12];
    const float* bo  = (const float*)d_in[13];
    float* out = (float*)d_out;

    size_t p_smem = (size_t)(8192 + 128*129 + 128) * sizeof(float);
    size_t m_smem = sizeof(SmemMain);
    cudaFuncSetAttribute(p_kernel,    cudaFuncAttributeMaxDynamicSharedMemorySize, (int)p_smem);
    cudaFuncSetAttribute(main_kernel, cudaFuncAttributeMaxDynamicSharedMemorySize, (int)m_smem);

    prep_kernel<<<64, 256>>>(aW1, Whh);
    p_kernel<<<BATCH, NTHR, p_smem>>>(X, aW1, ab1);
    main_kernel<<<NCTA, NTHR, m_smem>>>(X, Y, aW2, Wih, bih, bhh, Wfc, bfc, Wo, bo, out);
}

// round 7
// speedup vs baseline: 1.7254x; 1.1765x over previous
#include <cuda_runtime.h>
#include <cuda_bf16.h>

#define BATCH 256
#define TM1   63
#define NI    128
#define NH    128
#define GB    2
#define NCTA  (BATCH/GB)
#define NTHR  512
#define PPITCH 129

// Scratch (device globals: allocation-free rule)
__device__ float g_P[BATCH*TM1*NI];        // P[b][t][o] = aW1_x . X[b,t] + ab1
__device__ float g_WhhT[NH*4*NH];          // [128][512]  WhhT[k][j] = Whh[j][k]
__device__ float g_aW1hcT[2*NH*NI];        // [256][128]  aW1hcT[k][i] = aW1[i][k]

__device__ __forceinline__ float warp_sum(float v){
    v += __shfl_xor_sync(0xffffffffu, v, 16);
    v += __shfl_xor_sync(0xffffffffu, v, 8);
    v += __shfl_xor_sync(0xffffffffu, v, 4);
    v += __shfl_xor_sync(0xffffffffu, v, 2);
    v += __shfl_xor_sync(0xffffffffu, v, 1);
    return v;
}

__device__ __forceinline__ float ex2_approx(float x){
    float r;
    asm("ex2.approx.f32 %0, %1;" : "=f"(r) : "f"(x));
    return r;
}

// tanh: 2 MUFU (EX2 + RCP via fast div), few FFMA. rel err ~1e-6
__device__ __forceinline__ float ftanh(float x){
    float ax = fabsf(x);
    float e  = ex2_approx(ax * -2.885390082f);   // e^{-2ax}
    float t  = __fdividef(1.0f - e, 1.0f + e);
    return copysignf(t, x);
}
__device__ __forceinline__ float fsig(float x){
    return __fdividef(1.0f, 1.0f + ex2_approx(x * -1.442695041f));
}

// ---------------- prep: weight transposes ----------------
__global__ void prep_kernel(const float* __restrict__ aW1, const float* __restrict__ Whh){
    int tid = blockIdx.x*blockDim.x + threadIdx.x;
    int stride = gridDim.x*blockDim.x;
    for (int idx = tid; idx < 128*512; idx += stride){
        int k = idx >> 9, j = idx & 511;
        g_WhhT[idx] = Whh[j*128 + k];
    }
    for (int idx = tid; idx < 256*128; idx += stride){
        int k = idx >> 7, i = idx & 127;
        g_aW1hcT[idx] = aW1[i*384 + k];
    }
}

// ---------------- P precompute ----------------
__global__ void p_kernel(const float* __restrict__ X, const float* __restrict__ aW1,
                         const float* __restrict__ ab1){
    extern __shared__ char sraw[];
    float* Xs   = (float*)sraw;        // 8192 floats
    float* WT   = Xs + 8192;           // 128*129
    float* ab1s = WT + 128*129;        // 128
    int b = blockIdx.x, tid = threadIdx.x;
    const int PT = 256;

    for (int idx = tid; idx < 8192; idx += PT)
        Xs[idx] = (idx < TM1*NI) ? X[b*TM1*NI + idx] : 0.0f;
    for (int idx = tid; idx < 128*128; idx += PT){
        int o = idx >> 7, k = idx & 127;
        WT[k*129 + o] = aW1[o*384 + 256 + k];
    }
    if (tid < 128) ab1s[tid] = ab1[tid];
    __syncthreads();

    int o = tid & 127, half = tid >> 7;
    for (int tb = 0; tb < 8; tb++){
        int tbase = half*32 + tb*4;
        float bv = ab1s[o];
        float a0 = bv, a1 = bv, a2 = bv, a3 = bv;
        #pragma unroll 4
        for (int k = 0; k < 128; k++){
            float w = WT[k*129 + o];
            a0 = fmaf(Xs[(tbase+0)*128+k], w, a0);
            a1 = fmaf(Xs[(tbase+1)*128+k], w, a1);
            a2 = fmaf(Xs[(tbase+2)*128+k], w, a2);
            a3 = fmaf(Xs[(tbase+3)*128+k], w, a3);
        }
        if (tbase+0 < TM1) g_P[b*TM1*NI + (tbase+0)*128 + o] = a0;
        if (tbase+1 < TM1) g_P[b*TM1*NI + (tbase+1)*128 + o] = a1;
        if (tbase+2 < TM1) g_P[b*TM1*NI + (tbase+2)*128 + o] = a2;
        if (tbase+3 < TM1) g_P[b*TM1*NI + (tbase+3)*128 + o] = a3;
    }
}

// ---------------- main persistent recurrence ----------------
struct __align__(16) SmemMain {
    float Xs[GB][TM1][NI];        // 64512 B
    float Ps[GB][TM1][PPITCH];    // pitch 129, scalar access
    float qpart[8][GB][NI];
    float qs[GB][NI];
    float ctxpart[2][GB][NI];
    float gatesH[GB][4*NH];
    float aw2[NI];
    float wfc[132];               // [0..127]=Wfc[1..128], [128]=Wfc[0]
    float wo[2*NI];
    float hc[2*NH][GB];           // [k][g]; k<128: h, k>=128: c
    float scpart[4][GB][64];
    float be[GB][64];
    float XW[GB][64];             // XW[g][tt] = wfc . X[g][tt][:]
    float wih[4*NH];
    float bsum[4*NH];
    float Ys[GB][TM1+1];
    float rinv[GB];
    float yup[GB];
};

__global__ void __launch_bounds__(NTHR, 1) main_kernel(
    const float* __restrict__ X, const float* __restrict__ Y,
    const float* __restrict__ aW2,
    const float* __restrict__ Wih, const float* __restrict__ bih, const float* __restrict__ bhh,
    const float* __restrict__ Wfc, const float* __restrict__ bfc,
    const float* __restrict__ Wo,  const float* __restrict__ bo,
    float* __restrict__ out)
{
    extern __shared__ char smraw[];
    SmemMain* sm = (SmemMain*)smraw;
    int tid = threadIdx.x;
    int b0  = blockIdx.x * GB;
    int w = tid >> 5, lane = tid & 31;

    // ---- stage ----
    for (int idx = tid; idx < GB*TM1*NI; idx += NTHR){
        int g = idx / (TM1*NI), r = idx % (TM1*NI);
        int tt = r >> 7, i = r & 127;
        sm->Xs[g][tt][i] = X[b0*TM1*NI + idx];
        sm->Ps[g][tt][i] = g_P[b0*TM1*NI + idx];
    }
    for (int idx = tid; idx < 4*NH; idx += NTHR){
        sm->wih[idx]  = Wih[idx];
        sm->bsum[idx] = bih[idx] + bhh[idx];
    }
    for (int idx = tid; idx < GB*TM1; idx += NTHR){
        int g = idx / TM1, tt = idx % TM1;
        sm->Ys[g][tt] = Y[(b0+g)*TM1 + tt];
    }
    if (tid < NI)   sm->aw2[tid] = aW2[tid];
    if (tid < 128)  sm->wfc[tid] = Wfc[tid+1];
    if (tid == 128) sm->wfc[128] = Wfc[0];
    if (tid < 2*NI) sm->wo[tid]  = Wo[tid];
    for (int idx = tid; idx < 2*NH*GB; idx += NTHR) ((float*)sm->hc)[idx] = 0.0f;
    __syncthreads();

    // ---- one-time: XW[g][tt] = sum_i wfc[i]*Xs[g][tt][i] ----
    if (tid < GB*64){
        int g = tid >> 6, tt = tid & 63;
        float acc = 0.0f;
        if (tt < TM1){
            #pragma unroll 8
            for (int i = 0; i < NI; i++)
                acc = fmaf(sm->wfc[i], sm->Xs[g][tt][i], acc);
        }
        sm->XW[g][tt] = acc;   // tt=63 -> 0
    }
    __syncthreads();

    const float bfc0 = bfc[0];

    for (int t = 0; t < TM1; t++){
        // ======== phase 1: gates GEMV (1 j per thread) + q partials (8 k-slices) ========
        {
            const float* W    = g_WhhT;                    // [k][512]
            const float2* hcp = (const float2*)sm->hc;
            float a0 = 0.f, a1 = 0.f;
            #pragma unroll 16
            for (int k = 0; k < NH; k++){
                float wv = W[k*512 + tid];
                float2 h2 = hcp[k];
                a0 = fmaf(wv, h2.x, a0);
                a1 = fmaf(wv, h2.y, a1);
            }
            sm->gatesH[0][tid] = a0;
            sm->gatesH[1][tid] = a1;
        }
        {
            int qt = tid >> 6, il = tid & 63;              // qt in 0..7: 32-k slice
            const float2* W2  = (const float2*)g_aW1hcT;   // row k: 64 float2
            const float2* hcp = (const float2*)sm->hc;
            float a00=0.f, a01=0.f, a10=0.f, a11=0.f;
            #pragma unroll 16
            for (int kk = 0; kk < 32; kk++){
                int k = qt*32 + kk;
                float2 wv = W2[k*64 + il];
                float2 h2 = hcp[k];
                a00 = fmaf(wv.x, h2.x, a00); a01 = fmaf(wv.y, h2.x, a01);
                a10 = fmaf(wv.x, h2.y, a10); a11 = fmaf(wv.y, h2.y, a11);
            }
            sm->qpart[qt][0][2*il] = a00; sm->qpart[qt][0][2*il+1] = a01;
            sm->qpart[qt][1][2*il] = a10; sm->qpart[qt][1][2*il+1] = a11;
        }
        __syncthreads();
        // ======== phase 2: scores (thread = (g, quarter, tt), 32-wide dot) ========
        {
            int g   = tid >> 8;
            int qtr = (tid >> 6) & 3;
            int tt  = tid & 63;
            int ibase = qtr * 32;
            // warp-local q combine: lane covers i = ibase+lane (2 warps per (g,qtr) duplicate)
            {
                int i = ibase + lane;
                float s = sm->qpart[0][g][i] + sm->qpart[1][g][i]
                        + sm->qpart[2][g][i] + sm->qpart[3][g][i]
                        + sm->qpart[4][g][i] + sm->qpart[5][g][i]
                        + sm->qpart[6][g][i] + sm->qpart[7][g][i];
                sm->qs[g][i] = s;
            }
            __syncwarp();
            float acc = 0.0f;
            if (tt < TM1){
                const float* Prow = &sm->Ps[g][tt][ibase];
                const float* qrow = &sm->qs[g][ibase];
                const float* arow = &sm->aw2[ibase];
                #pragma unroll 8
                for (int i = 0; i < 32; i++)
                    acc = fmaf(arow[i], ftanh(Prow[i] + qrow[i]), acc);
            }
            sm->scpart[qtr][g][tt] = acc;
        }
        __syncthreads();
        // ======== phase 3: softmax + y_update (warps 0 and 8) ========
        if (w == 0 || w == 8){
            int g = w >> 3;
            float s0 = sm->scpart[0][g][lane] + sm->scpart[1][g][lane]
                     + sm->scpart[2][g][lane] + sm->scpart[3][g][lane];
            float s1 = (lane < 31) ? (sm->scpart[0][g][32+lane] + sm->scpart[1][g][32+lane]
                                    + sm->scpart[2][g][32+lane] + sm->scpart[3][g][32+lane])
                                   : -3.0e38f;
            float m = fmaxf(s0, s1);
            #pragma unroll
            for (int off = 16; off > 0; off >>= 1)
                m = fmaxf(m, __shfl_xor_sync(0xffffffffu, m, off));
            float e0 = ex2_approx((s0 - m) * 1.442695041f);
            float e1 = (lane < 31) ? ex2_approx((s1 - m) * 1.442695041f) : 0.0f;
            float sv = e0 + e1;
            float dv = e0 * sm->XW[g][lane] + e1 * sm->XW[g][32 + lane];
            #pragma unroll
            for (int off = 16; off > 0; off >>= 1){
                sv += __shfl_xor_sync(0xffffffffu, sv, off);
                dv += __shfl_xor_sync(0xffffffffu, dv, off);
            }
            sm->be[g][lane] = e0;
            if (lane < 31) sm->be[g][32+lane] = e1;
            if (lane == 0){
                float ri = __fdividef(1.0f, sv);
                sm->rinv[g] = ri;
                float yt = sm->Ys[g][t];
                sm->yup[g] = fmaf(dv, ri, fmaf(sm->wfc[128], yt, bfc0));
            }
        }
        __syncthreads();
        // ======== phase 4: LSTM cell only (context deferred to after the loop) ========
        if (tid < 256){
            int g = tid >> 7, i = tid & 127;
            float yu = sm->yup[g];
            float gi = sm->gatesH[g][i]        + yu*sm->wih[i]        + sm->bsum[i];
            float gf = sm->gatesH[g][NH+i]     + yu*sm->wih[NH+i]     + sm->bsum[NH+i];
            float gg = sm->gatesH[g][2*NH+i]   + yu*sm->wih[2*NH+i]   + sm->bsum[2*NH+i];
            float go = sm->gatesH[g][3*NH+i]   + yu*sm->wih[3*NH+i]   + sm->bsum[3*NH+i];
            float co = sm->hc[NH+i][g];
            float cn = fsig(gf)*co + fsig(gi)*ftanh(gg);
            float hn = fsig(go)*ftanh(cn);
            sm->hc[i][g]    = hn;
            sm->hc[NH+i][g] = cn;
        }
        __syncthreads();
    }

    // ---- final context from last step's be/rinv (split over 512 threads) ----
    {
        int g = tid >> 8, half = (tid >> 7) & 1, i = tid & 127;
        int t0 = half ? 32 : 0;
        int t1 = half ? TM1 : 32;
        float acc = 0.0f;
        for (int tt = t0; tt < t1; tt++)
            acc = fmaf(sm->be[g][tt], sm->Xs[g][tt][i], acc);
        sm->ctxpart[half][g][i] = acc;
    }
    __syncthreads();

    // ---- output: y[b] = bo + Wo[0:128].h + Wo[128:256].ctx  (warps 0 and 8) ----
    if (w == 0 || w == 8){
        int g = w >> 3;
        float ri = sm->rinv[g];
        float acc = 0.0f;
        #pragma unroll
        for (int r = 0; r < 4; r++){
            int i = lane*4 + r;
            float ctx = (sm->ctxpart[0][g][i] + sm->ctxpart[1][g][i]) * ri;
            acc += sm->wo[i]*sm->hc[i][g] + sm->wo[NI+i]*ctx;
        }
        acc = warp_sum(acc);
        if (lane == 0) out[b0 + g] = acc + bo[0];
    }
}

extern "C" void kernel_launch(void* const* d_in, const int* in_sizes, int n_in,
                              void* d_out, int out_size) {
    const float* X   = (const float*)d_in[0];
    const float* Y   = (const float*)d_in[1];
    const float* aW1 = (const float*)d_in[2];
    const float* ab1 = (const float*)d_in[3];
    const float* aW2 = (const float*)d_in[4];
    // d_in[5] = ab2: constant softmax shift, mathematically irrelevant
    const float* Wih = (const float*)d_in[6];
    const float* Whh = (const float*)d_in[7];
    const float* bih = (const float*)d_in[8];
    const float* bhh = (const float*)d_in[9];
    const float* Wfc = (const float*)d_in[10];
    const float* bfc = (const float*)d_in[11];
    const float* Wo  = (const float*)d_in[12];
    const float* bo  = (const float*)d_in[13];
    float* out = (float*)d_out;

    size_t p_smem = (size_t)(8192 + 128*129 + 128) * sizeof(float);
    size_t m_smem = sizeof(SmemMain);
    cudaFuncSetAttribute(p_kernel,    cudaFuncAttributeMaxDynamicSharedMemorySize, (int)p_smem);
    cudaFuncSetAttribute(main_kernel, cudaFuncAttributeMaxDynamicSharedMemorySize, (int)m_smem);

    prep_kernel<<<64, 256>>>(aW1, Whh);
    p_kernel<<<BATCH, 256, p_smem>>>(X, aW1, ab1);
    main_kernel<<<NCTA, NTHR, m_smem>>>(X, Y, aW2, Wih, bih, bhh, Wfc, bfc, Wo, bo, out);
}

// round 9
// speedup vs baseline: 1.8938x; 1.0976x over previous
#include <cuda_runtime.h>
#include <cuda_fp16.h>
#include <cuda_bf16.h>

#define BATCH 256
#define TM1   63
#define NI    128
#define NH    128
#define GB    2
#define NCTA  (BATCH/GB)
#define NTHR  512
#define PPITCH 129

// Scratch (device globals: allocation-free rule)
__device__ float   g_P[BATCH*TM1*NI];      // P[b][t][o] = aW1_x . X[b,t] + ab1
__device__ __half2 g_Whh16[64*512];        // [k2][j] = (Whh[j][2k2], Whh[j][2k2+1])
__device__ float   g_aW1hcT[2*NH*NI];      // [256][128]  aW1hcT[k][i] = aW1[i][k]

__device__ __forceinline__ float warp_sum(float v){
    v += __shfl_xor_sync(0xffffffffu, v, 16);
    v += __shfl_xor_sync(0xffffffffu, v, 8);
    v += __shfl_xor_sync(0xffffffffu, v, 4);
    v += __shfl_xor_sync(0xffffffffu, v, 2);
    v += __shfl_xor_sync(0xffffffffu, v, 1);
    return v;
}

__device__ __forceinline__ float ex2_approx(float x){
    float r;
    asm("ex2.approx.f32 %0, %1;" : "=f"(r) : "f"(x));
    return r;
}

// tanh: 2 MUFU (EX2 + RCP via fast div). rel err ~1e-6
__device__ __forceinline__ float ftanh(float x){
    float ax = fabsf(x);
    float e  = ex2_approx(ax * -2.885390082f);   // e^{-2ax}
    float t  = __fdividef(1.0f - e, 1.0f + e);
    return copysignf(t, x);
}
__device__ __forceinline__ float fsig(float x){
    return __fdividef(1.0f, 1.0f + ex2_approx(x * -1.442695041f));
}

// ---------------- prep: weight transposes / packing ----------------
__global__ void prep_kernel(const float* __restrict__ aW1, const float* __restrict__ Whh){
    int tid = blockIdx.x*blockDim.x + threadIdx.x;
    int stride = gridDim.x*blockDim.x;
    // interleaved fp16 pairs: g_Whh16[k2*512 + j] = (Whh[j][2k2], Whh[j][2k2+1])
    for (int idx = tid; idx < 64*512; idx += stride){
        int k2 = idx >> 9, j = idx & 511;
        g_Whh16[idx] = __floats2half2_rn(Whh[j*128 + 2*k2], Whh[j*128 + 2*k2 + 1]);
    }
    for (int idx = tid; idx < 256*128; idx += stride){
        int k = idx >> 7, i = idx & 127;
        g_aW1hcT[idx] = aW1[i*384 + k];
    }
}

// ---------------- P precompute ----------------
__global__ void p_kernel(const float* __restrict__ X, const float* __restrict__ aW1,
                         const float* __restrict__ ab1){
    extern __shared__ char sraw[];
    float* Xs   = (float*)sraw;        // 8192 floats
    float* WT   = Xs + 8192;           // 128*129
    float* ab1s = WT + 128*129;        // 128
    int b = blockIdx.x, tid = threadIdx.x;
    const int PT = 256;

    for (int idx = tid; idx < 8192; idx += PT)
        Xs[idx] = (idx < TM1*NI) ? X[b*TM1*NI + idx] : 0.0f;
    for (int idx = tid; idx < 128*128; idx += PT){
        int o = idx >> 7, k = idx & 127;
        WT[k*129 + o] = aW1[o*384 + 256 + k];
    }
    if (tid < 128) ab1s[tid] = ab1[tid];
    __syncthreads();

    int o = tid & 127, half = tid >> 7;
    for (int tb = 0; tb < 8; tb++){
        int tbase = half*32 + tb*4;
        float bv = ab1s[o];
        float a0 = bv, a1 = bv, a2 = bv, a3 = bv;
        #pragma unroll 4
        for (int k = 0; k < 128; k++){
            float w = WT[k*129 + o];
            a0 = fmaf(Xs[(tbase+0)*128+k], w, a0);
            a1 = fmaf(Xs[(tbase+1)*128+k], w, a1);
            a2 = fmaf(Xs[(tbase+2)*128+k], w, a2);
            a3 = fmaf(Xs[(tbase+3)*128+k], w, a3);
        }
        if (tbase+0 < TM1) g_P[b*TM1*NI + (tbase+0)*128 + o] = a0;
        if (tbase+1 < TM1) g_P[b*TM1*NI + (tbase+1)*128 + o] = a1;
        if (tbase+2 < TM1) g_P[b*TM1*NI + (tbase+2)*128 + o] = a2;
        if (tbase+3 < TM1) g_P[b*TM1*NI + (tbase+3)*128 + o] = a3;
    }
}

// ---------------- main persistent recurrence ----------------
struct __align__(16) SmemMain {
    __half2 Whh16[64*512];        // 131072 B — SMEM-resident recurrent weights
    float Ps[GB][TM1][PPITCH];    // 65016 B, pitch 129
    float qpart[8][GB][NI];
    float qs[GB][NI];
    float ctxpart[2][GB][NI];
    float gatesH[GB][4*NH];
    float aw2[NI];
    float wfc[132];               // [0..127]=Wfc[1..128], [128]=Wfc[0]
    float wo[2*NI];
    float hc[2*NH][GB];           // [k][g]; k<128: h, k>=128: c
    float scpart[4][GB][64];
    float be[GB][64];
    float XW[GB][64];             // XW[g][tt] = wfc . X[g][tt][:]
    float wih[4*NH];
    float bsum[4*NH];
    float Ys[GB][TM1+1];
    float rinv[GB];
    float yup[GB];
};

__global__ void __launch_bounds__(NTHR, 1) main_kernel(
    const float* __restrict__ X, const float* __restrict__ Y,
    const float* __restrict__ aW2,
    const float* __restrict__ Wih, const float* __restrict__ bih, const float* __restrict__ bhh,
    const float* __restrict__ Wfc, const float* __restrict__ bfc,
    const float* __restrict__ Wo,  const float* __restrict__ bo,
    float* __restrict__ out)
{
    extern __shared__ char smraw[];
    SmemMain* sm = (SmemMain*)smraw;
    int tid = threadIdx.x;
    int b0  = blockIdx.x * GB;
    int w = tid >> 5, lane = tid & 31;

    // ---- stage: Whh16 (coalesced 16B; 4 half2 per uint4 -> 8192 uint4), Ps, weights ----
    {
        const uint4* src = (const uint4*)g_Whh16;
        uint4* dst = (uint4*)sm->Whh16;
        #pragma unroll 4
        for (int idx = tid; idx < 8192; idx += NTHR)
            dst[idx] = src[idx];
    }
    for (int idx = tid; idx < GB*TM1*NI; idx += NTHR){
        int g = idx / (TM1*NI), r = idx % (TM1*NI);
        int tt = r >> 7, i = r & 127;
        sm->Ps[g][tt][i] = g_P[b0*TM1*NI + idx];
    }
    for (int idx = tid; idx < 4*NH; idx += NTHR){
        sm->wih[idx]  = Wih[idx];
        sm->bsum[idx] = bih[idx] + bhh[idx];
    }
    for (int idx = tid; idx < GB*TM1; idx += NTHR){
        int g = idx / TM1, tt = idx % TM1;
        sm->Ys[g][tt] = Y[(b0+g)*TM1 + tt];
    }
    if (tid < NI)   sm->aw2[tid] = aW2[tid];
    if (tid < 128)  sm->wfc[tid] = Wfc[tid+1];
    if (tid == 128) sm->wfc[128] = Wfc[0];
    if (tid < 2*NI) sm->wo[tid]  = Wo[tid];
    for (int idx = tid; idx < 2*NH*GB; idx += NTHR) ((float*)sm->hc)[idx] = 0.0f;
    __syncthreads();

    // ---- one-time: XW[g][tt] = sum_i wfc[i]*X[g][tt][i]  (X from global) ----
    if (tid < GB*64){
        int g = tid >> 6, tt = tid & 63;
        float acc = 0.0f;
        if (tt < TM1){
            const float* Xrow = X + (b0+g)*TM1*NI + tt*NI;
            #pragma unroll 8
            for (int i = 0; i < NI; i++)
                acc = fmaf(sm->wfc[i], Xrow[i], acc);
        }
        sm->XW[g][tt] = acc;   // tt=63 -> 0
    }
    __syncthreads();

    const float bfc0 = bfc[0];

    for (int t = 0; t < TM1; t++){
        // ======== phase 1: gates GEMV from SMEM fp16 + q partials from L2 fp32 ========
        {
            const __half2* W  = sm->Whh16;                 // [k2*512 + j]
            const float2* hcp = (const float2*)sm->hc;     // (h_g0, h_g1)
            float a0 = 0.f, a1 = 0.f;
            #pragma unroll 16
            for (int k2 = 0; k2 < 64; k2++){
                float2 wf = __half22float2(W[k2*512 + tid]);
                float2 ha = hcp[2*k2];
                float2 hb = hcp[2*k2+1];
                a0 = fmaf(wf.x, ha.x, a0); a0 = fmaf(wf.y, hb.x, a0);
                a1 = fmaf(wf.x, ha.y, a1); a1 = fmaf(wf.y, hb.y, a1);
            }
            sm->gatesH[0][tid] = a0;
            sm->gatesH[1][tid] = a1;
        }
        {
            int qt = tid >> 6, il = tid & 63;              // qt in 0..7: 32-k slice
            const float2* W2  = (const float2*)g_aW1hcT;   // row k: 64 float2
            const float2* hcp = (const float2*)sm->hc;
            float a00=0.f, a01=0.f, a10=0.f, a11=0.f;
            #pragma unroll 16
            for (int kk = 0; kk < 32; kk++){
                int k = qt*32 + kk;
                float2 wv = W2[k*64 + il];
                float2 h2 = hcp[k];
                a00 = fmaf(wv.x, h2.x, a00); a01 = fmaf(wv.y, h2.x, a01);
                a10 = fmaf(wv.x, h2.y, a10); a11 = fmaf(wv.y, h2.y, a11);
            }
            sm->qpart[qt][0][2*il] = a00; sm->qpart[qt][0][2*il+1] = a01;
            sm->qpart[qt][1][2*il] = a10; sm->qpart[qt][1][2*il+1] = a11;
        }
        __syncthreads();
        // ======== phase 2: scores (thread = (g, quarter, tt), 32-wide dot) ========
        {
            int g   = tid >> 8;
            int qtr = (tid >> 6) & 3;
            int tt  = tid & 63;
            int ibase = qtr * 32;
            {
                int i = ibase + lane;
                float s = sm->qpart[0][g][i] + sm->qpart[1][g][i]
                        + sm->qpart[2][g][i] + sm->qpart[3][g][i]
                        + sm->qpart[4][g][i] + sm->qpart[5][g][i]
                        + sm->qpart[6][g][i] + sm->qpart[7][g][i];
                sm->qs[g][i] = s;
            }
            __syncwarp();
            float acc = 0.0f;
            if (tt < TM1){
                const float* Prow = &sm->Ps[g][tt][ibase];
                const float* qrow = &sm->qs[g][ibase];
                const float* arow = &sm->aw2[ibase];
                #pragma unroll 8
                for (int i = 0; i < 32; i++)
                    acc = fmaf(arow[i], ftanh(Prow[i] + qrow[i]), acc);
            }
            sm->scpart[qtr][g][tt] = acc;
        }
        __syncthreads();
        // ======== phase 3: softmax + y_update (warps 0 and 8) ========
        if (w == 0 || w == 8){
            int g = w >> 3;
            float s0 = sm->scpart[0][g][lane] + sm->scpart[1][g][lane]
                     + sm->scpart[2][g][lane] + sm->scpart[3][g][lane];
            float s1 = (lane < 31) ? (sm->scpart[0][g][32+lane] + sm->scpart[1][g][32+lane]
                                    + sm->scpart[2][g][32+lane] + sm->scpart[3][g][32+lane])
                                   : -3.0e38f;
            float m = fmaxf(s0, s1);
            #pragma unroll
            for (int off = 16; off > 0; off >>= 1)
                m = fmaxf(m, __shfl_xor_sync(0xffffffffu, m, off));
            float e0 = ex2_approx((s0 - m) * 1.442695041f);
            float e1 = (lane < 31) ? ex2_approx((s1 - m) * 1.442695041f) : 0.0f;
            float sv = e0 + e1;
            float dv = e0 * sm->XW[g][lane] + e1 * sm->XW[g][32 + lane];
            #pragma unroll
            for (int off = 16; off > 0; off >>= 1){
                sv += __shfl_xor_sync(0xffffffffu, sv, off);
                dv += __shfl_xor_sync(0xffffffffu, dv, off);
            }
            sm->be[g][lane] = e0;
            if (lane < 31) sm->be[g][32+lane] = e1;
            if (lane == 0){
                float ri = __fdividef(1.0f, sv);
                sm->rinv[g] = ri;
                float yt = sm->Ys[g][t];
                sm->yup[g] = fmaf(dv, ri, fmaf(sm->wfc[128], yt, bfc0));
            }
        }
        __syncthreads();
        // ======== phase 4: LSTM cell (context deferred past the loop) ========
        if (tid < 256){
            int g = tid >> 7, i = tid & 127;
            float yu = sm->yup[g];
            float gi = sm->gatesH[g][i]        + yu*sm->wih[i]        + sm->bsum[i];
            float gf = sm->gatesH[g][NH+i]     + yu*sm->wih[NH+i]     + sm->bsum[NH+i];
            float gg = sm->gatesH[g][2*NH+i]   + yu*sm->wih[2*NH+i]   + sm->bsum[2*NH+i];
            float go = sm->gatesH[g][3*NH+i]   + yu*sm->wih[3*NH+i]   + sm->bsum[3*NH+i];
            float co = sm->hc[NH+i][g];
            float cn = fsig(gf)*co + fsig(gi)*ftanh(gg);
            float hn = fsig(go)*ftanh(cn);
            sm->hc[i][g]    = hn;
            sm->hc[NH+i][g] = cn;
        }
        __syncthreads();
    }

    // ---- final context from last step's be/rinv (X from global, coalesced in i) ----
    {
        int g = tid >> 8, half = (tid >> 7) & 1, i = tid & 127;
        int t0 = half ? 32 : 0;
        int t1 = half ? TM1 : 32;
        const float* Xg = X + (b0+g)*TM1*NI;
        float acc = 0.0f;
        for (int tt = t0; tt < t1; tt++)
            acc = fmaf(sm->be[g][tt], Xg[tt*NI + i], acc);
        sm->ctxpart[half][g][i] = acc;
    }
    __syncthreads();

    // ---- output: y[b] = bo + Wo[0:128].h + Wo[128:256].ctx  (warps 0 and 8) ----
    if (w == 0 || w == 8){
        int g = w >> 3;
        float ri = sm->rinv[g];
        float acc = 0.0f;
        #pragma unroll
        for (int r = 0; r < 4; r++){
            int i = lane*4 + r;
            float ctx = (sm->ctxpart[0][g][i] + sm->ctxpart[1][g][i]) * ri;
            acc += sm->wo[i]*sm->hc[i][g] + sm->wo[NI+i]*ctx;
        }
        acc = warp_sum(acc);
        if (lane == 0) out[b0 + g] = acc + bo[0];
    }
}

extern "C" void kernel_launch(void* const* d_in, const int* in_sizes, int n_in,
                              void* d_out, int out_size) {
    const float* X   = (const float*)d_in[0];
    const float* Y   = (const float*)d_in[1];
    const float* aW1 = (const float*)d_in[2];
    const float* ab1 = (const float*)d_in[3];
    const float* aW2 = (const float*)d_in[4];
    // d_in[5] = ab2: constant softmax shift, mathematically irrelevant
    const float* Wih = (const float*)d_in[6];
    const float* Whh = (const float*)d_in[7];
    const float* bih = (const float*)d_in[8];
    const float* bhh = (const float*)d_in[9];
    const float* Wfc = (const float*)d_in[10];
    const float* bfc = (const float*)d_in[11];
    const float* Wo  = (const float*)d_in[12];
    const float* bo  = (const float*)d_in[13];
    float* out = (float*)d_out;

    size_t p_smem = (size_t)(8192 + 128*129 + 128) * sizeof(float);
    size_t m_smem = sizeof(SmemMain);
    cudaFuncSetAttribute(p_kernel,    cudaFuncAttributeMaxDynamicSharedMemorySize, (int)p_smem);
    cudaFuncSetAttribute(main_kernel, cudaFuncAttributeMaxDynamicSharedMemorySize, (int)m_smem);

    prep_kernel<<<64, 256>>>(aW1, Whh);
    p_kernel<<<BATCH, 256, p_smem>>>(X, aW1, ab1);
    main_kernel<<<NCTA, NTHR, m_smem>>>(X, Y, aW2, Wih, bih, bhh, Wfc, bfc, Wo, bo, out);
}

// round 10
// speedup vs baseline: 2.1992x; 1.1613x over previous
#include <cuda_runtime.h>
#include <cuda_fp16.h>
#include <cuda_bf16.h>

#define BATCH 256
#define TM1   63
#define NI    128
#define NH    128
#define GB    2
#define NCTA  (BATCH/GB)
#define NTHR  512
#define PPITCH 129

// Scratch (device globals: allocation-free rule)
__device__ float   g_P[BATCH*TM1*NI];      // P[b][t][o] = aW1_x . X[b,t] + ab1
__device__ __half2 g_Whh16[64*512];        // [k2][j] = (Whh[j][2k2], Whh[j][2k2+1])
__device__ __half2 g_aW1hc16[256*64];      // [k][i2] = (aW1[2i2][k], aW1[2i2+1][k])

__device__ __forceinline__ float warp_sum(float v){
    v += __shfl_xor_sync(0xffffffffu, v, 16);
    v += __shfl_xor_sync(0xffffffffu, v, 8);
    v += __shfl_xor_sync(0xffffffffu, v, 4);
    v += __shfl_xor_sync(0xffffffffu, v, 2);
    v += __shfl_xor_sync(0xffffffffu, v, 1);
    return v;
}

__device__ __forceinline__ float ex2_approx(float x){
    float r;
    asm("ex2.approx.f32 %0, %1;" : "=f"(r) : "f"(x));
    return r;
}
// 1-MUFU hardware tanh (scores only: one-shot path, no recurrent accumulation)
__device__ __forceinline__ float tanh_approx(float x){
    float r;
    asm("tanh.approx.f32 %0, %1;" : "=f"(r) : "f"(x));
    return r;
}
// accurate tanh/sigmoid for the recurrent LSTM path
__device__ __forceinline__ float ftanh(float x){
    float ax = fabsf(x);
    float e  = ex2_approx(ax * -2.885390082f);
    float t  = __fdividef(1.0f - e, 1.0f + e);
    return copysignf(t, x);
}
__device__ __forceinline__ float fsig(float x){
    return __fdividef(1.0f, 1.0f + ex2_approx(x * -1.442695041f));
}

// ---------------- prep: weight transposes / packing ----------------
__global__ void prep_kernel(const float* __restrict__ aW1, const float* __restrict__ Whh){
    int tid = blockIdx.x*blockDim.x + threadIdx.x;
    int stride = gridDim.x*blockDim.x;
    for (int idx = tid; idx < 64*512; idx += stride){
        int k2 = idx >> 9, j = idx & 511;
        g_Whh16[idx] = __floats2half2_rn(Whh[j*128 + 2*k2], Whh[j*128 + 2*k2 + 1]);
    }
    // q weights fp16: [k][i2] pairs over i
    for (int idx = tid; idx < 256*64; idx += stride){
        int k = idx >> 6, i2 = idx & 63;
        g_aW1hc16[idx] = __floats2half2_rn(aW1[(2*i2)*384 + k], aW1[(2*i2+1)*384 + k]);
    }
}

// ---------------- P precompute ----------------
__global__ void p_kernel(const float* __restrict__ X, const float* __restrict__ aW1,
                         const float* __restrict__ ab1){
    extern __shared__ char sraw[];
    float* Xs   = (float*)sraw;        // 8192 floats
    float* WT   = Xs + 8192;           // 128*129
    float* ab1s = WT + 128*129;        // 128
    int b = blockIdx.x, tid = threadIdx.x;
    const int PT = 256;

    for (int idx = tid; idx < 8192; idx += PT)
        Xs[idx] = (idx < TM1*NI) ? X[b*TM1*NI + idx] : 0.0f;
    for (int idx = tid; idx < 128*128; idx += PT){
        int o = idx >> 7, k = idx & 127;
        WT[k*129 + o] = aW1[o*384 + 256 + k];
    }
    if (tid < 128) ab1s[tid] = ab1[tid];
    __syncthreads();

    int o = tid & 127, half = tid >> 7;
    for (int tb = 0; tb < 8; tb++){
        int tbase = half*32 + tb*4;
        float bv = ab1s[o];
        float a0 = bv, a1 = bv, a2 = bv, a3 = bv;
        #pragma unroll 4
        for (int k = 0; k < 128; k++){
            float w = WT[k*129 + o];
            a0 = fmaf(Xs[(tbase+0)*128+k], w, a0);
            a1 = fmaf(Xs[(tbase+1)*128+k], w, a1);
            a2 = fmaf(Xs[(tbase+2)*128+k], w, a2);
            a3 = fmaf(Xs[(tbase+3)*128+k], w, a3);
        }
        if (tbase+0 < TM1) g_P[b*TM1*NI + (tbase+0)*128 + o] = a0;
        if (tbase+1 < TM1) g_P[b*TM1*NI + (tbase+1)*128 + o] = a1;
        if (tbase+2 < TM1) g_P[b*TM1*NI + (tbase+2)*128 + o] = a2;
        if (tbase+3 < TM1) g_P[b*TM1*NI + (tbase+3)*128 + o] = a3;
    }
}

// ---------------- main persistent recurrence ----------------
struct __align__(16) SmemMain {
    __half2 Whh16[64*512];        // 131072 B
    float Ps[GB][TM1][PPITCH];    // 65016 B (== 8 mod 16)
    float _pad0[2];               // restore 16B alignment for all following arrays
    float qpart[8][GB][NI];
    float qs[GB][NI];
    float ctxpart[2][GB][NI];
    float gatesH[GB][4*NH];
    float aw2[NI];
    float wfc[132];               // [0..127]=Wfc[1..128], [128]=Wfc[0]; 528B (16-mult)
    float wo[2*NI];
    float hc[2*NH][GB];           // [k][g]; 16B-aligned -> float4 loads over k pairs
    float scpart[4][GB][64];
    float be[GB][64];
    float XW[GB][64];
    float wih[4*NH];
    float bsum[4*NH];
    float Ys[GB][TM1+1];
    float rinv[GB];
    float yup[GB];
};

__global__ void __launch_bounds__(NTHR, 1) main_kernel(
    const float* __restrict__ X, const float* __restrict__ Y,
    const float* __restrict__ aW2,
    const float* __restrict__ Wih, const float* __restrict__ bih, const float* __restrict__ bhh,
    const float* __restrict__ Wfc, const float* __restrict__ bfc,
    const float* __restrict__ Wo,  const float* __restrict__ bo,
    float* __restrict__ out)
{
    extern __shared__ char smraw[];
    SmemMain* sm = (SmemMain*)smraw;
    int tid = threadIdx.x;
    int b0  = blockIdx.x * GB;
    int w = tid >> 5, lane = tid & 31;

    // ---- stage: Whh16 (131072B = 8192 uint4), Ps, small weights ----
    {
        const uint4* src = (const uint4*)g_Whh16;
        uint4* dst = (uint4*)sm->Whh16;
        #pragma unroll 4
        for (int idx = tid; idx < 8192; idx += NTHR)
            dst[idx] = src[idx];
    }
    for (int idx = tid; idx < GB*TM1*NI; idx += NTHR){
        int g = idx / (TM1*NI), r = idx % (TM1*NI);
        int tt = r >> 7, i = r & 127;
        sm->Ps[g][tt][i] = g_P[b0*TM1*NI + idx];
    }
    for (int idx = tid; idx < 4*NH; idx += NTHR){
        sm->wih[idx]  = Wih[idx];
        sm->bsum[idx] = bih[idx] + bhh[idx];
    }
    for (int idx = tid; idx < GB*TM1; idx += NTHR){
        int g = idx / TM1, tt = idx % TM1;
        sm->Ys[g][tt] = Y[(b0+g)*TM1 + tt];
    }
    if (tid < NI)   sm->aw2[tid] = aW2[tid];
    if (tid < 128)  sm->wfc[tid] = Wfc[tid+1];
    if (tid == 128) sm->wfc[128] = Wfc[0];
    if (tid < 2*NI) sm->wo[tid]  = Wo[tid];
    for (int idx = tid; idx < 2*NH*GB; idx += NTHR) ((float*)sm->hc)[idx] = 0.0f;
    __syncthreads();

    // ---- one-time: XW[g][tt] = wfc . X[g][tt][:]  (X from global) ----
    if (tid < GB*64){
        int g = tid >> 6, tt = tid & 63;
        float acc = 0.0f;
        if (tt < TM1){
            const float* Xrow = X + (b0+g)*TM1*NI + tt*NI;
            #pragma unroll 8
            for (int i = 0; i < NI; i++)
                acc = fmaf(sm->wfc[i], Xrow[i], acc);
        }
        sm->XW[g][tt] = acc;   // tt=63 -> 0
    }
    __syncthreads();

    const float bfc0 = bfc[0];

    for (int t = 0; t < TM1; t++){
        // ======== phase 1: gates GEMV (SMEM fp16, float4 hc) + q partials (L2 fp16) ========
        {
            const __half2* W   = sm->Whh16;                // [k2*512 + j]
            const float4*  hc4 = (const float4*)sm->hc;    // k2 -> (h2k[0],h2k[1],h2k1[0],h2k1[1])
            float a0 = 0.f, a1 = 0.f;
            #pragma unroll 16
            for (int k2 = 0; k2 < 64; k2++){
                float2 wf = __half22float2(W[k2*512 + tid]);
                float4 hq = hc4[k2];
                a0 = fmaf(wf.x, hq.x, a0); a0 = fmaf(wf.y, hq.z, a0);
                a1 = fmaf(wf.x, hq.y, a1); a1 = fmaf(wf.y, hq.w, a1);
            }
            sm->gatesH[0][tid] = a0;
            sm->gatesH[1][tid] = a1;
        }
        {
            int qt = tid >> 6, il = tid & 63;              // qt: 32-k slice, il: i-pair
            const float2* hcp = (const float2*)sm->hc;
            float a00=0.f, a01=0.f, a10=0.f, a11=0.f;
            #pragma unroll 16
            for (int kk = 0; kk < 32; kk++){
                int k = qt*32 + kk;
                float2 wv = __half22float2(g_aW1hc16[k*64 + il]);
                float2 h2 = hcp[k];
                a00 = fmaf(wv.x, h2.x, a00); a01 = fmaf(wv.y, h2.x, a01);
                a10 = fmaf(wv.x, h2.y, a10); a11 = fmaf(wv.y, h2.y, a11);
            }
            sm->qpart[qt][0][2*il] = a00; sm->qpart[qt][0][2*il+1] = a01;
            sm->qpart[qt][1][2*il] = a10; sm->qpart[qt][1][2*il+1] = a11;
        }
        __syncthreads();
        // ======== phase 2: scores (thread = (g, quarter, tt), 32-wide dot) ========
        {
            int g   = tid >> 8;
            int qtr = (tid >> 6) & 3;
            int tt  = tid & 63;
            int ibase = qtr * 32;
            {
                int i = ibase + lane;
                float s = sm->qpart[0][g][i] + sm->qpart[1][g][i]
                        + sm->qpart[2][g][i] + sm->qpart[3][g][i]
                        + sm->qpart[4][g][i] + sm->qpart[5][g][i]
                        + sm->qpart[6][g][i] + sm->qpart[7][g][i];
                sm->qs[g][i] = s;
            }
            __syncwarp();
            float acc = 0.0f;
            if (tt < TM1){
                const float* Prow = &sm->Ps[g][tt][ibase];
                const float* qrow = &sm->qs[g][ibase];
                const float* arow = &sm->aw2[ibase];
                #pragma unroll 8
                for (int i = 0; i < 32; i++)
                    acc = fmaf(arow[i], tanh_approx(Prow[i] + qrow[i]), acc);
            }
            sm->scpart[qtr][g][tt] = acc;
        }
        __syncthreads();
        // ======== phase 3: softmax + y_update (warps 0 and 8) ========
        if (w == 0 || w == 8){
            int g = w >> 3;
            float s0 = sm->scpart[0][g][lane] + sm->scpart[1][g][lane]
                     + sm->scpart[2][g][lane] + sm->scpart[3][g][lane];
            float s1 = (lane < 31) ? (sm->scpart[0][g][32+lane] + sm->scpart[1][g][32+lane]
                                    + sm->scpart[2][g][32+lane] + sm->scpart[3][g][32+lane])
                                   : -3.0e38f;
            float m = fmaxf(s0, s1);
            #pragma unroll
            for (int off = 16; off > 0; off >>= 1)
                m = fmaxf(m, __shfl_xor_sync(0xffffffffu, m, off));
            float e0 = ex2_approx((s0 - m) * 1.442695041f);
            float e1 = (lane < 31) ? ex2_approx((s1 - m) * 1.442695041f) : 0.0f;
            float sv = e0 + e1;
            float dv = e0 * sm->XW[g][lane] + e1 * sm->XW[g][32 + lane];
            #pragma unroll
            for (int off = 16; off > 0; off >>= 1){
                sv += __shfl_xor_sync(0xffffffffu, sv, off);
                dv += __shfl_xor_sync(0xffffffffu, dv, off);
            }
            sm->be[g][lane] = e0;
            if (lane < 31) sm->be[g][32+lane] = e1;
            if (lane == 0){
                float ri = __fdividef(1.0f, sv);
                sm->rinv[g] = ri;
                float yt = sm->Ys[g][t];
                sm->yup[g] = fmaf(dv, ri, fmaf(sm->wfc[128], yt, bfc0));
            }
        }
        __syncthreads();
        // ======== phase 4: LSTM cell (accurate activations; context deferred) ========
        if (tid < 256){
            int g = tid >> 7, i = tid & 127;
            float yu = sm->yup[g];
            float gi = sm->gatesH[g][i]        + yu*sm->wih[i]        + sm->bsum[i];
            float gf = sm->gatesH[g][NH+i]     + yu*sm->wih[NH+i]     + sm->bsum[NH+i];
            float gg = sm->gatesH[g][2*NH+i]   + yu*sm->wih[2*NH+i]   + sm->bsum[2*NH+i];
            float go = sm->gatesH[g][3*NH+i]   + yu*sm->wih[3*NH+i]   + sm->bsum[3*NH+i];
            float co = sm->hc[NH+i][g];
            float cn = fsig(gf)*co + fsig(gi)*ftanh(gg);
            float hn = fsig(go)*ftanh(cn);
            sm->hc[i][g]    = hn;
            sm->hc[NH+i][g] = cn;
        }
        __syncthreads();
    }

    // ---- final context from last step's be/rinv (X from global) ----
    {
        int g = tid >> 8, half = (tid >> 7) & 1, i = tid & 127;
        int t0 = half ? 32 : 0;
        int t1 = half ? TM1 : 32;
        const float* Xg = X + (b0+g)*TM1*NI;
        float acc = 0.0f;
        for (int tt = t0; tt < t1; tt++)
            acc = fmaf(sm->be[g][tt], Xg[tt*NI + i], acc);
        sm->ctxpart[half][g][i] = acc;
    }
    __syncthreads();

    // ---- output: y[b] = bo + Wo[0:128].h + Wo[128:256].ctx  (warps 0 and 8) ----
    if (w == 0 || w == 8){
        int g = w >> 3;
        float ri = sm->rinv[g];
        float acc = 0.0f;
        #pragma unroll
        for (int r = 0; r < 4; r++){
            int i = lane*4 + r;
            float ctx = (sm->ctxpart[0][g][i] + sm->ctxpart[1][g][i]) * ri;
            acc += sm->wo[i]*sm->hc[i][g] + sm->wo[NI+i]*ctx;
        }
        acc = warp_sum(acc);
        if (lane == 0) out[b0 + g] = acc + bo[0];
    }
}

extern "C" void kernel_launch(void* const* d_in, const int* in_sizes, int n_in,
                              void* d_out, int out_size) {
    const float* X   = (const float*)d_in[0];
    const float* Y   = (const float*)d_in[1];
    const float* aW1 = (const float*)d_in[2];
    const float* ab1 = (const float*)d_in[3];
    const float* aW2 = (const float*)d_in[4];
    // d_in[5] = ab2: constant softmax shift, mathematically irrelevant
    const float* Wih = (const float*)d_in[6];
    const float* Whh = (const float*)d_in[7];
    const float* bih = (const float*)d_in[8];
    const float* bhh = (const float*)d_in[9];
    const float* Wfc = (const float*)d_in[10];
    const float* bfc = (const float*)d_in[11];
    const float* Wo  = (const float*)d_in[12];
    const float* bo  = (const float*)d_in[13];
    float* out = (float*)d_out;

    size_t p_smem = (size_t)(8192 + 128*129 + 128) * sizeof(float);
    size_t m_smem = sizeof(SmemMain);
    cudaFuncSetAttribute(p_kernel,    cudaFuncAttributeMaxDynamicSharedMemorySize, (int)p_smem);
    cudaFuncSetAttribute(main_kernel, cudaFuncAttributeMaxDynamicSharedMemorySize, (int)m_smem);

    prep_kernel<<<64, 256>>>(aW1, Whh);
    p_kernel<<<BATCH, 256, p_smem>>>(X, aW1, ab1);
    main_kernel<<<NCTA, NTHR, m_smem>>>(X, Y, aW2, Wih, bih, bhh, Wfc, bfc, Wo, bo, out);
}

// round 12
// speedup vs baseline: 3.1366x; 1.4262x over previous
#include <cuda_runtime.h>
#include <cuda_fp16.h>
#include <cuda_bf16.h>
#include <cstdint>

#define BATCH 256
#define TM1   63
#define NI    128
#define NH    128
#define GB    2
#define NCTA  (BATCH/GB)
#define NTHR  512
#define PPITCH 129

typedef unsigned int u32;

// Scratch (device globals: allocation-free rule)
__device__ float   g_P[BATCH*TM1*NI];      // P[b][t][o] = aW1_x . X[b,t] + ab1
__device__ __half2 g_Whh16[512*64];        // j-major: [j][k2] = (Whh[j][2k2], Whh[j][2k2+1])
__device__ float   g_aW1hcT[2*NH*NI];      // [k][i] fp32: aW1hcT[k][i] = aW1[i][k]

__device__ __forceinline__ float warp_sum(float v){
    v += __shfl_xor_sync(0xffffffffu, v, 16);
    v += __shfl_xor_sync(0xffffffffu, v, 8);
    v += __shfl_xor_sync(0xffffffffu, v, 4);
    v += __shfl_xor_sync(0xffffffffu, v, 2);
    v += __shfl_xor_sync(0xffffffffu, v, 1);
    return v;
}

__device__ __forceinline__ float ex2_approx(float x){
    float r;
    asm("ex2.approx.f32 %0, %1;" : "=f"(r) : "f"(x));
    return r;
}
// 1-MUFU hardware tanh (scores only)
__device__ __forceinline__ float tanh_approx(float x){
    float r;
    asm("tanh.approx.f32 %0, %1;" : "=f"(r) : "f"(x));
    return r;
}
// accurate tanh/sigmoid for the recurrent LSTM path
__device__ __forceinline__ float ftanh(float x){
    float ax = fabsf(x);
    float e  = ex2_approx(ax * -2.885390082f);
    float t  = __fdividef(1.0f - e, 1.0f + e);
    return copysignf(t, x);
}
__device__ __forceinline__ float fsig(float x){
    return __fdividef(1.0f, 1.0f + ex2_approx(x * -1.442695041f));
}

// m16n8k16 row.col f32 = f16*f16 + f32
#define MMA16816(d, a, b0, b1)                                              \
    asm volatile("mma.sync.aligned.m16n8k16.row.col.f32.f16.f16.f32 "       \
        "{%0,%1,%2,%3}, {%4,%5,%6,%7}, {%8,%9}, {%0,%1,%2,%3};"             \
        : "+f"((d)[0]), "+f"((d)[1]), "+f"((d)[2]), "+f"((d)[3])            \
        : "r"((a)[0]), "r"((a)[1]), "r"((a)[2]), "r"((a)[3]),               \
          "r"(b0), "r"(b1))

// ---------------- prep: weight transposes / packing ----------------
__global__ void prep_kernel(const float* __restrict__ aW1, const float* __restrict__ Whh){
    int tid = blockIdx.x*blockDim.x + threadIdx.x;
    int stride = gridDim.x*blockDim.x;
    // j-major fp16 pairs for HMMA A fragments
    for (int idx = tid; idx < 512*64; idx += stride){
        int j = idx >> 6, k2 = idx & 63;
        g_Whh16[idx] = __floats2half2_rn(Whh[j*128 + 2*k2], Whh[j*128 + 2*k2 + 1]);
    }
    // q weights fp32 transpose [k][i]
    for (int idx = tid; idx < 256*128; idx += stride){
        int k = idx >> 7, i = idx & 127;
        g_aW1hcT[idx] = aW1[i*384 + k];
    }
}

// ---------------- P precompute ----------------
__global__ void p_kernel(const float* __restrict__ X, const float* __restrict__ aW1,
                         const float* __restrict__ ab1){
    extern __shared__ char sraw[];
    float* Xs   = (float*)sraw;        // 8192 floats
    float* WT   = Xs + 8192;           // 128*129
    float* ab1s = WT + 128*129;        // 128
    int b = blockIdx.x, tid = threadIdx.x;
    const int PT = 256;

    for (int idx = tid; idx < 8192; idx += PT)
        Xs[idx] = (idx < TM1*NI) ? X[b*TM1*NI + idx] : 0.0f;
    for (int idx = tid; idx < 128*128; idx += PT){
        int o = idx >> 7, k = idx & 127;
        WT[k*129 + o] = aW1[o*384 + 256 + k];
    }
    if (tid < 128) ab1s[tid] = ab1[tid];
    __syncthreads();

    int o = tid & 127, half = tid >> 7;
    for (int tb = 0; tb < 8; tb++){
        int tbase = half*32 + tb*4;
        float bv = ab1s[o];
        float a0 = bv, a1 = bv, a2 = bv, a3 = bv;
        #pragma unroll 4
        for (int k = 0; k < 128; k++){
            float w = WT[k*129 + o];
            a0 = fmaf(Xs[(tbase+0)*128+k], w, a0);
            a1 = fmaf(Xs[(tbase+1)*128+k], w, a1);
            a2 = fmaf(Xs[(tbase+2)*128+k], w, a2);
            a3 = fmaf(Xs[(tbase+3)*128+k], w, a3);
        }
        if (tbase+0 < TM1) g_P[b*TM1*NI + (tbase+0)*128 + o] = a0;
        if (tbase+1 < TM1) g_P[b*TM1*NI + (tbase+1)*128 + o] = a1;
        if (tbase+2 < TM1) g_P[b*TM1*NI + (tbase+2)*128 + o] = a2;
        if (tbase+3 < TM1) g_P[b*TM1*NI + (tbase+3)*128 + o] = a3;
    }
}

// ---------------- main persistent recurrence ----------------
struct __align__(16) SmemMain {
    float aWhc[256*128];          // 131072 B — q weights fp32, SMEM-resident
    float Ps[GB][TM1][PPITCH];    // 65016 B
    float _pad0[2];
    float qpart[8][GB][NI];
    float qs[GB][NI];
    float ctxpart[2][GB][NI];
    float gatesH[GB][4*NH];
    float aw2[NI];
    float wfc[132];               // [0..127]=Wfc[1..128], [128]=Wfc[0]
    float wo[2*NI];
    float hc[2*NH][GB];           // fp32 [k][g]
    __half hc16[GB][NH];          // fp16 h for HMMA B operand
    float scpart[4][GB][64];
    float be[GB][64];
    float XW[GB][64];
    float wih[4*NH];
    float bsum[4*NH];
    float Ys[GB][TM1+1];
    float rinv[GB];
    float yup[GB];
};

__global__ void __launch_bounds__(NTHR, 1) main_kernel(
    const float* __restrict__ X, const float* __restrict__ Y,
    const float* __restrict__ aW2,
    const float* __restrict__ Wih, const float* __restrict__ bih, const float* __restrict__ bhh,
    const float* __restrict__ Wfc, const float* __restrict__ bfc,
    const float* __restrict__ Wo,  const float* __restrict__ bo,
    float* __restrict__ out)
{
    extern __shared__ char smraw[];
    SmemMain* sm = (SmemMain*)smraw;
    int tid = threadIdx.x;
    int b0  = blockIdx.x * GB;
    int w = tid >> 5, lane = tid & 31;

    // ---- persistent A fragments: Whh fp16, 2 Mtiles x 8 ktiles x 4 regs ----
    u32 Af[2][8][4];
    {
        const u32* Wg = (const u32*)g_Whh16;  // [j*64 + k2]
        int r = lane >> 2, cq = lane & 3;
        #pragma unroll
        for (int m = 0; m < 2; m++){
            int j0 = w*32 + m*16;
            #pragma unroll
            for (int kt = 0; kt < 8; kt++){
                int base = kt*8 + cq;
                Af[m][kt][0] = Wg[(j0 + r)*64     + base];
                Af[m][kt][1] = Wg[(j0 + 8 + r)*64 + base];
                Af[m][kt][2] = Wg[(j0 + r)*64     + base + 4];
                Af[m][kt][3] = Wg[(j0 + 8 + r)*64 + base + 4];
            }
        }
    }

    // ---- stage: q weights fp32 (131072B = 8192 uint4), Ps, small weights ----
    {
        const uint4* src = (const uint4*)g_aW1hcT;
        uint4* dst = (uint4*)sm->aWhc;
        #pragma unroll 4
        for (int idx = tid; idx < 8192; idx += NTHR)
            dst[idx] = src[idx];
    }
    for (int idx = tid; idx < GB*TM1*NI; idx += NTHR){
        int g = idx / (TM1*NI), r = idx % (TM1*NI);
        int tt = r >> 7, i = r & 127;
        sm->Ps[g][tt][i] = g_P[b0*TM1*NI + idx];
    }
    for (int idx = tid; idx < 4*NH; idx += NTHR){
        sm->wih[idx]  = Wih[idx];
        sm->bsum[idx] = bih[idx] + bhh[idx];
    }
    for (int idx = tid; idx < GB*TM1; idx += NTHR){
        int g = idx / TM1, tt = idx % TM1;
        sm->Ys[g][tt] = Y[(b0+g)*TM1 + tt];
    }
    if (tid < NI)   sm->aw2[tid] = aW2[tid];
    if (tid < 128)  sm->wfc[tid] = Wfc[tid+1];
    if (tid == 128) sm->wfc[128] = Wfc[0];
    if (tid < 2*NI) sm->wo[tid]  = Wo[tid];
    for (int idx = tid; idx < 2*NH*GB; idx += NTHR) ((float*)sm->hc)[idx] = 0.0f;
    if (tid < GB*NH) ((__half*)sm->hc16)[tid] = __float2half(0.0f);
    __syncthreads();

    // ---- one-time: XW[g][tt] = wfc . X[g][tt][:]  (X from global) ----
    if (tid < GB*64){
        int g = tid >> 6, tt = tid & 63;
        float acc = 0.0f;
        if (tt < TM1){
            const float* Xrow = X + (b0+g)*TM1*NI + tt*NI;
            #pragma unroll 8
            for (int i = 0; i < NI; i++)
                acc = fmaf(sm->wfc[i], Xrow[i], acc);
        }
        sm->XW[g][tt] = acc;
    }
    __syncthreads();

    const float bfc0 = bfc[0];

    for (int t = 0; t < TM1; t++){
        // ======== phase 1a: gates GEMV via HMMA (A in regs, B = hc16) ========
        {
            float d0[4] = {0.f,0.f,0.f,0.f};
            float d1[4] = {0.f,0.f,0.f,0.f};
            // B fragment: col = lane>>2 (only cols 0,1 = g used), k-rows via lane&3
            const __half* h16 = sm->hc16[(lane >> 2) & 1];
            int koff = (lane & 3) * 2;
            #pragma unroll
            for (int kt = 0; kt < 8; kt++){
                u32 bb0 = *(const u32*)&h16[kt*16 + koff];
                u32 bb1 = *(const u32*)&h16[kt*16 + koff + 8];
                MMA16816(d0, Af[0][kt], bb0, bb1);
                MMA16816(d1, Af[1][kt], bb0, bb1);
            }
            if ((lane & 3) == 0){
                int rr = lane >> 2;
                int j0 = w*32;
                sm->gatesH[0][j0 + rr]      = d0[0];
                sm->gatesH[1][j0 + rr]      = d0[1];
                sm->gatesH[0][j0 + 8 + rr]  = d0[2];
                sm->gatesH[1][j0 + 8 + rr]  = d0[3];
                sm->gatesH[0][j0 + 16 + rr] = d1[0];
                sm->gatesH[1][j0 + 16 + rr] = d1[1];
                sm->gatesH[0][j0 + 24 + rr] = d1[2];
                sm->gatesH[1][j0 + 24 + rr] = d1[3];
            }
        }
        // ======== phase 1b: q partials (SMEM fp32) ========
        {
            int qt = tid >> 6, il = tid & 63;              // qt: 32-k slice, il: i-pair
            const float2* W2  = (const float2*)sm->aWhc;   // row k: 64 float2
            const float2* hcp = (const float2*)sm->hc;
            float a00=0.f, a01=0.f, a10=0.f, a11=0.f;
            #pragma unroll 16
            for (int kk = 0; kk < 32; kk++){
                int k = qt*32 + kk;
                float2 wv = W2[k*64 + il];
                float2 h2 = hcp[k];
                a00 = fmaf(wv.x, h2.x, a00); a01 = fmaf(wv.y, h2.x, a01);
                a10 = fmaf(wv.x, h2.y, a10); a11 = fmaf(wv.y, h2.y, a11);
            }
            sm->qpart[qt][0][2*il] = a00; sm->qpart[qt][0][2*il+1] = a01;
            sm->qpart[qt][1][2*il] = a10; sm->qpart[qt][1][2*il+1] = a11;
        }
        __syncthreads();
        // ======== phase 2: scores (thread = (g, quarter, tt), 32-wide dot) ========
        {
            int g   = tid >> 8;
            int qtr = (tid >> 6) & 3;
            int tt  = tid & 63;
            int ibase = qtr * 32;
            {
                int i = ibase + lane;
                float s = sm->qpart[0][g][i] + sm->qpart[1][g][i]
                        + sm->qpart[2][g][i] + sm->qpart[3][g][i]
                        + sm->qpart[4][g][i] + sm->qpart[5][g][i]
                        + sm->qpart[6][g][i] + sm->qpart[7][g][i];
                sm->qs[g][i] = s;
            }
            __syncwarp();
            float acc = 0.0f;
            if (tt < TM1){
                const float* Prow = &sm->Ps[g][tt][ibase];
                const float* qrow = &sm->qs[g][ibase];
                const float* arow = &sm->aw2[ibase];
                #pragma unroll 8
                for (int i = 0; i < 32; i++)
                    acc = fmaf(arow[i], tanh_approx(Prow[i] + qrow[i]), acc);
            }
            sm->scpart[qtr][g][tt] = acc;
        }
        __syncthreads();
        // ======== phase 3: softmax (no max-sub; scores bounded) + y_update ========
        if (w == 0 || w == 8){
            int g = w >> 3;
            float s0 = sm->scpart[0][g][lane] + sm->scpart[1][g][lane]
                     + sm->scpart[2][g][lane] + sm->scpart[3][g][lane];
            float e0 = ex2_approx(s0 * 1.442695041f);
            float e1 = 0.0f;
            if (lane < 31){
                float s1 = sm->scpart[0][g][32+lane] + sm->scpart[1][g][32+lane]
                         + sm->scpart[2][g][32+lane] + sm->scpart[3][g][32+lane];
                e1 = ex2_approx(s1 * 1.442695041f);
            }
            float sv = e0 + e1;
            float dv = e0 * sm->XW[g][lane] + e1 * sm->XW[g][32 + lane];
            #pragma unroll
            for (int off = 16; off > 0; off >>= 1){
                sv += __shfl_xor_sync(0xffffffffu, sv, off);
                dv += __shfl_xor_sync(0xffffffffu, dv, off);
            }
            if (t == TM1-1){
                sm->be[g][lane] = e0;
                if (lane < 31) sm->be[g][32+lane] = e1;
            }
            if (lane == 0){
                float ri = __fdividef(1.0f, sv);
                sm->rinv[g] = ri;
                float yt = sm->Ys[g][t];
                sm->yup[g] = fmaf(dv, ri, fmaf(sm->wfc[128], yt, bfc0));
            }
        }
        __syncthreads();
        // ======== phase 4: LSTM cell (accurate activations) ========
        if (tid < 256){
            int g = tid >> 7, i = tid & 127;
            float yu = sm->yup[g];
            float gi = sm->gatesH[g][i]        + yu*sm->wih[i]        + sm->bsum[i];
            float gf = sm->gatesH[g][NH+i]     + yu*sm->wih[NH+i]     + sm->bsum[NH+i];
            float gg = sm->gatesH[g][2*NH+i]   + yu*sm->wih[2*NH+i]   + sm->bsum[2*NH+i];
            float go = sm->gatesH[g][3*NH+i]   + yu*sm->wih[3*NH+i]   + sm->bsum[3*NH+i];
            float co = sm->hc[NH+i][g];
            float cn = fsig(gf)*co + fsig(gi)*ftanh(gg);
            float hn = fsig(go)*ftanh(cn);
            sm->hc[i][g]    = hn;
            sm->hc[NH+i][g] = cn;
            sm->hc16[g][i]  = __float2half(hn);
        }
        __syncthreads();
    }

    // ---- final context from last step's be/rinv (X from global) ----
    {
        int g = tid >> 8, half = (tid >> 7) & 1, i = tid & 127;
        int t0 = half ? 32 : 0;
        int t1 = half ? TM1 : 32;
        const float* Xg = X + (b0+g)*TM1*NI;
        float acc = 0.0f;
        for (int tt = t0; tt < t1; tt++)
            acc = fmaf(sm->be[g][tt], Xg[tt*NI + i], acc);
        sm->ctxpart[half][g][i] = acc;
    }
    __syncthreads();

    // ---- output: y[b] = bo + Wo[0:128].h + Wo[128:256].ctx  (warps 0 and 8) ----
    if (w == 0 || w == 8){
        int g = w >> 3;
        float ri = sm->rinv[g];
        float acc = 0.0f;
        #pragma unroll
        for (int r = 0; r < 4; r++){
            int i = lane*4 + r;
            float ctx = (sm->ctxpart[0][g][i] + sm->ctxpart[1][g][i]) * ri;
            acc += sm->wo[i]*sm->hc[i][g] + sm->wo[NI+i]*ctx;
        }
        acc = warp_sum(acc);
        if (lane == 0) out[b0 + g] = acc + bo[0];
    }
}

extern "C" void kernel_launch(void* const* d_in, const int* in_sizes, int n_in,
                              void* d_out, int out_size) {
    const float* X   = (const float*)d_in[0];
    const float* Y   = (const float*)d_in[1];
    const float* aW1 = (const float*)d_in[2];
    const float* ab1 = (const float*)d_in[3];
    const float* aW2 = (const float*)d_in[4];
    // d_in[5] = ab2: constant softmax shift, mathematically irrelevant
    const float* Wih = (const float*)d_in[6];
    const float* Whh = (const float*)d_in[7];
    const float* bih = (const float*)d_in[8];
    const float* bhh = (const float*)d_in[9];
    const float* Wfc = (const float*)d_in[10];
    const float* bfc = (const float*)d_in[11];
    const float* Wo  = (const float*)d_in[12];
    const float* bo  = (const float*)d_in[13];
    float* out = (float*)d_out;

    size_t p_smem = (size_t)(8192 + 128*129 + 128) * sizeof(float);
    size_t m_smem = sizeof(SmemMain);
    cudaFuncSetAttribute(p_kernel,    cudaFuncAttributeMaxDynamicSharedMemorySize, (int)p_smem);
    cudaFuncSetAttribute(main_kernel, cudaFuncAttributeMaxDynamicSharedMemorySize, (int)m_smem);

    prep_kernel<<<64, 256>>>(aW1, Whh);
    p_kernel<<<BATCH, 256, p_smem>>>(X, aW1, ab1);
    main_kernel<<<NCTA, NTHR, m_smem>>>(X, Y, aW2, Wih, bih, bhh, Wfc, bfc, Wo, bo, out);
}

// round 14
// speedup vs baseline: 3.8707x; 1.2341x over previous
#include <cuda_runtime.h>
#include <cuda_fp16.h>
#include <cuda_bf16.h>
#include <cstdint>

#define BATCH 256
#define TM1   63
#define NI    128
#define NH    128
#define GB    2
#define NCTA  (BATCH/GB)
#define NTHR  512
#define PPITCH 129

typedef unsigned int u32;

// Scratch (device globals: allocation-free rule)
__device__ float   g_P[BATCH*TM1*NI];      // P[b][t][o] = aW1_x . X[b,t] + ab1
__device__ __half2 g_Whh16[512*64];        // j-major: [j][k2] = (Whh[j][2k2], Whh[j][2k2+1])
__device__ __half2 g_aW1hc16[128*128];     // i-major: [i][k2] = (aW1[i][2k2], aW1[i][2k2+1]), k<256

__device__ __forceinline__ float warp_sum(float v){
    v += __shfl_xor_sync(0xffffffffu, v, 16);
    v += __shfl_xor_sync(0xffffffffu, v, 8);
    v += __shfl_xor_sync(0xffffffffu, v, 4);
    v += __shfl_xor_sync(0xffffffffu, v, 2);
    v += __shfl_xor_sync(0xffffffffu, v, 1);
    return v;
}

__device__ __forceinline__ float ex2_approx(float x){
    float r;
    asm("ex2.approx.f32 %0, %1;" : "=f"(r) : "f"(x));
    return r;
}
// 1-MUFU hardware tanh (scores only)
__device__ __forceinline__ float tanh_approx(float x){
    float r;
    asm("tanh.approx.f32 %0, %1;" : "=f"(r) : "f"(x));
    return r;
}
// accurate tanh/sigmoid for the recurrent LSTM path
__device__ __forceinline__ float ftanh(float x){
    float ax = fabsf(x);
    float e  = ex2_approx(ax * -2.885390082f);
    float t  = __fdividef(1.0f - e, 1.0f + e);
    return copysignf(t, x);
}
__device__ __forceinline__ float fsig(float x){
    return __fdividef(1.0f, 1.0f + ex2_approx(x * -1.442695041f));
}

// m16n8k16 row.col f32 = f16*f16 + f32
#define MMA16816(d, a, b0, b1)                                              \
    asm volatile("mma.sync.aligned.m16n8k16.row.col.f32.f16.f16.f32 "       \
        "{%0,%1,%2,%3}, {%4,%5,%6,%7}, {%8,%9}, {%0,%1,%2,%3};"             \
        : "+f"((d)[0]), "+f"((d)[1]), "+f"((d)[2]), "+f"((d)[3])            \
        : "r"((a)[0]), "r"((a)[1]), "r"((a)[2]), "r"((a)[3]),               \
          "r"(b0), "r"(b1))

// ---------------- prep: weight packing ----------------
__global__ void prep_kernel(const float* __restrict__ aW1, const float* __restrict__ Whh){
    int tid = blockIdx.x*blockDim.x + threadIdx.x;
    int stride = gridDim.x*blockDim.x;
    for (int idx = tid; idx < 512*64; idx += stride){
        int j = idx >> 6, k2 = idx & 63;
        g_Whh16[idx] = __floats2half2_rn(Whh[j*128 + 2*k2], Whh[j*128 + 2*k2 + 1]);
    }
    // q weights fp16, i-major over k<256 (the [h;c] part of aW1)
    for (int idx = tid; idx < 128*128; idx += stride){
        int i = idx >> 7, k2 = idx & 127;
        g_aW1hc16[idx] = __floats2half2_rn(aW1[i*384 + 2*k2], aW1[i*384 + 2*k2 + 1]);
    }
}

// ---------------- P precompute ----------------
__global__ void p_kernel(const float* __restrict__ X, const float* __restrict__ aW1,
                         const float* __restrict__ ab1){
    extern __shared__ char sraw[];
    float* Xs   = (float*)sraw;        // 8192 floats
    float* WT   = Xs + 8192;           // 128*129
    float* ab1s = WT + 128*129;        // 128
    int b = blockIdx.x, tid = threadIdx.x;
    const int PT = 256;

    for (int idx = tid; idx < 8192; idx += PT)
        Xs[idx] = (idx < TM1*NI) ? X[b*TM1*NI + idx] : 0.0f;
    for (int idx = tid; idx < 128*128; idx += PT){
        int o = idx >> 7, k = idx & 127;
        WT[k*129 + o] = aW1[o*384 + 256 + k];
    }
    if (tid < 128) ab1s[tid] = ab1[tid];
    __syncthreads();

    int o = tid & 127, half = tid >> 7;
    for (int tb = 0; tb < 8; tb++){
        int tbase = half*32 + tb*4;
        float bv = ab1s[o];
        float a0 = bv, a1 = bv, a2 = bv, a3 = bv;
        #pragma unroll 4
        for (int k = 0; k < 128; k++){
            float w = WT[k*129 + o];
            a0 = fmaf(Xs[(tbase+0)*128+k], w, a0);
            a1 = fmaf(Xs[(tbase+1)*128+k], w, a1);
            a2 = fmaf(Xs[(tbase+2)*128+k], w, a2);
            a3 = fmaf(Xs[(tbase+3)*128+k], w, a3);
        }
        if (tbase+0 < TM1) g_P[b*TM1*NI + (tbase+0)*128 + o] = a0;
        if (tbase+1 < TM1) g_P[b*TM1*NI + (tbase+1)*128 + o] = a1;
        if (tbase+2 < TM1) g_P[b*TM1*NI + (tbase+2)*128 + o] = a2;
        if (tbase+3 < TM1) g_P[b*TM1*NI + (tbase+3)*128 + o] = a3;
    }
}

// ---------------- main persistent recurrence ----------------
struct __align__(16) SmemMain {
    float Ps[GB][TM1][PPITCH];    // 65016 B
    float _pad0[2];
    float qs[GB][NI];
    float ctxpart[2][GB][NI];
    float gatesH[GB][4*NH];
    float aw2[NI];
    float wfc[132];               // [0..127]=Wfc[1..128], [128]=Wfc[0]
    float wo[2*NI];
    float hc[2*NH][GB];           // fp32 [k][g]
    __half hc16x[GB][2*NH];       // fp16 [h;c] for HMMA B operand: h@[0..127], c@[128..255]
    float scpart[4][GB][64];
    float be[GB][64];
    float XW[GB][64];
    float wih[4*NH];
    float bsum[4*NH];
    float Ys[GB][TM1+1];
    float rinv[GB];
    float yup[GB];
};

__global__ void __launch_bounds__(NTHR, 1) main_kernel(
    const float* __restrict__ X, const float* __restrict__ Y,
    const float* __restrict__ aW2,
    const float* __restrict__ Wih, const float* __restrict__ bih, const float* __restrict__ bhh,
    const float* __restrict__ Wfc, const float* __restrict__ bfc,
    const float* __restrict__ Wo,  const float* __restrict__ bo,
    float* __restrict__ out)
{
    extern __shared__ char smraw[];
    SmemMain* sm = (SmemMain*)smraw;
    int tid = threadIdx.x;
    int b0  = blockIdx.x * GB;
    int w = tid >> 5, lane = tid & 31;

    // ---- persistent A fragments: 96 regs/thread, balanced ----
    // w<8 : Af[0..2] = gates m-tiles at rows w*48 + m*16 (k-tiles 0..7 of h)
    // w>=8: Af[0]    = gates m-tile at rows 384 + (w-8)*16
    //       Af[1]    = q m-tile rows (w-8)*16, k-tiles 0..7  (h part)
    //       Af[2]    = q m-tile same rows,     k-tiles 8..15 (c part)
    u32 Af[3][8][4];
    {
        const u32* Wg = (const u32*)g_Whh16;    // [j*64 + k2]
        const u32* Qg = (const u32*)g_aW1hc16;  // [i*128 + k2]
        int r = lane >> 2, cq = lane & 3;
        if (w < 8){
            #pragma unroll
            for (int m = 0; m < 3; m++){
                int j0 = w*48 + m*16;
                #pragma unroll
                for (int kt = 0; kt < 8; kt++){
                    int base = kt*8 + cq;
                    Af[m][kt][0] = Wg[(j0 + r)*64     + base];
                    Af[m][kt][1] = Wg[(j0 + 8 + r)*64 + base];
                    Af[m][kt][2] = Wg[(j0 + r)*64     + base + 4];
                    Af[m][kt][3] = Wg[(j0 + 8 + r)*64 + base + 4];
                }
            }
        } else {
            int j0 = 384 + (w-8)*16;
            int i0 = (w-8)*16;
            #pragma unroll
            for (int kt = 0; kt < 8; kt++){
                int base = kt*8 + cq;
                Af[0][kt][0] = Wg[(j0 + r)*64     + base];
                Af[0][kt][1] = Wg[(j0 + 8 + r)*64 + base];
                Af[0][kt][2] = Wg[(j0 + r)*64     + base + 4];
                Af[0][kt][3] = Wg[(j0 + 8 + r)*64 + base + 4];
                Af[1][kt][0] = Qg[(i0 + r)*128     + base];
                Af[1][kt][1] = Qg[(i0 + 8 + r)*128 + base];
                Af[1][kt][2] = Qg[(i0 + r)*128     + base + 4];
                Af[1][kt][3] = Qg[(i0 + 8 + r)*128 + base + 4];
                int base2 = 64 + kt*8 + cq;
                Af[2][kt][0] = Qg[(i0 + r)*128     + base2];
                Af[2][kt][1] = Qg[(i0 + 8 + r)*128 + base2];
                Af[2][kt][2] = Qg[(i0 + r)*128     + base2 + 4];
                Af[2][kt][3] = Qg[(i0 + 8 + r)*128 + base2 + 4];
            }
        }
    }

    // ---- stage: Ps, small weights ----
    for (int idx = tid; idx < GB*TM1*NI; idx += NTHR){
        int g = idx / (TM1*NI), r = idx % (TM1*NI);
        int tt = r >> 7, i = r & 127;
        sm->Ps[g][tt][i] = g_P[b0*TM1*NI + idx];
    }
    for (int idx = tid; idx < 4*NH; idx += NTHR){
        sm->wih[idx]  = Wih[idx];
        sm->bsum[idx] = bih[idx] + bhh[idx];
    }
    for (int idx = tid; idx < GB*TM1; idx += NTHR){
        int g = idx / TM1, tt = idx % TM1;
        sm->Ys[g][tt] = Y[(b0+g)*TM1 + tt];
    }
    if (tid < NI)   sm->aw2[tid] = aW2[tid];
    if (tid < 128)  sm->wfc[tid] = Wfc[tid+1];
    if (tid == 128) sm->wfc[128] = Wfc[0];
    if (tid < 2*NI) sm->wo[tid]  = Wo[tid];
    for (int idx = tid; idx < 2*NH*GB; idx += NTHR) ((float*)sm->hc)[idx] = 0.0f;
    for (int idx = tid; idx < GB*2*NH; idx += NTHR) ((__half*)sm->hc16x)[idx] = __float2half(0.0f);
    __syncthreads();

    // ---- one-time: XW[g][tt] = wfc . X[g][tt][:]  (X from global) ----
    if (tid < GB*64){
        int g = tid >> 6, tt = tid & 63;
        float acc = 0.0f;
        if (tt < TM1){
            const float* Xrow = X + (b0+g)*TM1*NI + tt*NI;
            #pragma unroll 8
            for (int i = 0; i < NI; i++)
                acc = fmaf(sm->wfc[i], Xrow[i], acc);
        }
        sm->XW[g][tt] = acc;
    }
    __syncthreads();

    const float bfc0 = bfc[0];

    for (int t = 0; t < TM1; t++){
        // ======== phase 1: gates + q via HMMA (A in regs, B = hc16x) ========
        {
            // B: col = lane>>2 (only 0,1 = g valid), k via lane&3
            const __half* hA = sm->hc16x[(lane >> 2) & 1];
            int koff = (lane & 3) * 2;
            if (w < 8){
                float d0[4] = {0.f,0.f,0.f,0.f};
                float d1[4] = {0.f,0.f,0.f,0.f};
                float d2[4] = {0.f,0.f,0.f,0.f};
                #pragma unroll
                for (int kt = 0; kt < 8; kt++){
                    u32 bb0 = *(const u32*)&hA[kt*16 + koff];
                    u32 bb1 = *(const u32*)&hA[kt*16 + koff + 8];
                    MMA16816(d0, Af[0][kt], bb0, bb1);
                    MMA16816(d1, Af[1][kt], bb0, bb1);
                    MMA16816(d2, Af[2][kt], bb0, bb1);
                }
                if ((lane & 3) == 0){
                    int rr = lane >> 2;
                    int j0 = w*48;
                    sm->gatesH[0][j0 + rr]       = d0[0];
                    sm->gatesH[1][j0 + rr]       = d0[1];
                    sm->gatesH[0][j0 + 8 + rr]   = d0[2];
                    sm->gatesH[1][j0 + 8 + rr]   = d0[3];
                    sm->gatesH[0][j0 + 16 + rr]  = d1[0];
                    sm->gatesH[1][j0 + 16 + rr]  = d1[1];
                    sm->gatesH[0][j0 + 24 + rr]  = d1[2];
                    sm->gatesH[1][j0 + 24 + rr]  = d1[3];
                    sm->gatesH[0][j0 + 32 + rr]  = d2[0];
                    sm->gatesH[1][j0 + 32 + rr]  = d2[1];
                    sm->gatesH[0][j0 + 40 + rr]  = d2[2];
                    sm->gatesH[1][j0 + 40 + rr]  = d2[3];
                }
            } else {
                float dg[4] = {0.f,0.f,0.f,0.f};
                float dq[4] = {0.f,0.f,0.f,0.f};
                #pragma unroll
                for (int kt = 0; kt < 8; kt++){
                    u32 bb0 = *(const u32*)&hA[kt*16 + koff];
                    u32 bb1 = *(const u32*)&hA[kt*16 + koff + 8];
                    MMA16816(dg, Af[0][kt], bb0, bb1);
                    MMA16816(dq, Af[1][kt], bb0, bb1);
                }
                // c part of [h;c] lives at hA[128 + k]  (k-tiles 8..15)
                #pragma unroll
                for (int kt = 0; kt < 8; kt++){
                    u32 bb0 = *(const u32*)&hA[128 + kt*16 + koff];
                    u32 bb1 = *(const u32*)&hA[128 + kt*16 + koff + 8];
                    MMA16816(dq, Af[2][kt], bb0, bb1);
                }
                if ((lane & 3) == 0){
                    int rr = lane >> 2;
                    int j0 = 384 + (w-8)*16;
                    int i0 = (w-8)*16;
                    sm->gatesH[0][j0 + rr]      = dg[0];
                    sm->gatesH[1][j0 + rr]      = dg[1];
                    sm->gatesH[0][j0 + 8 + rr]  = dg[2];
                    sm->gatesH[1][j0 + 8 + rr]  = dg[3];
                    sm->qs[0][i0 + rr]          = dq[0];
                    sm->qs[1][i0 + rr]          = dq[1];
                    sm->qs[0][i0 + 8 + rr]      = dq[2];
                    sm->qs[1][i0 + 8 + rr]      = dq[3];
                }
            }
        }
        __syncthreads();
        // ======== phase 2: scores (thread = (g, quarter, tt), 32-wide dot) ========
        {
            int g   = tid >> 8;
            int qtr = (tid >> 6) & 3;
            int tt  = tid & 63;
            int ibase = qtr * 32;
            float acc = 0.0f;
            if (tt < TM1){
                const float* Prow = &sm->Ps[g][tt][ibase];
                const float* qrow = &sm->qs[g][ibase];
                const float* arow = &sm->aw2[ibase];
                #pragma unroll 8
                for (int i = 0; i < 32; i++)
                    acc = fmaf(arow[i], tanh_approx(Prow[i] + qrow[i]), acc);
            }
            sm->scpart[qtr][g][tt] = acc;
        }
        __syncthreads();
        // ======== phase 3: softmax (no max-sub; scores bounded) + y_update ========
        if (w == 0 || w == 8){
            int g = w >> 3;
            float s0 = sm->scpart[0][g][lane] + sm->scpart[1][g][lane]
                     + sm->scpart[2][g][lane] + sm->scpart[3][g][lane];
            float e0 = ex2_approx(s0 * 1.442695041f);
            float e1 = 0.0f;
            if (lane < 31){
                float s1 = sm->scpart[0][g][32+lane] + sm->scpart[1][g][32+lane]
                         + sm->scpart[2][g][32+lane] + sm->scpart[3][g][32+lane];
                e1 = ex2_approx(s1 * 1.442695041f);
            }
            float sv = e0 + e1;
            float dv = e0 * sm->XW[g][lane] + e1 * sm->XW[g][32 + lane];
            #pragma unroll
            for (int off = 16; off > 0; off >>= 1){
                sv += __shfl_xor_sync(0xffffffffu, sv, off);
                dv += __shfl_xor_sync(0xffffffffu, dv, off);
            }
            if (t == TM1-1){
                sm->be[g][lane] = e0;
                if (lane < 31) sm->be[g][32+lane] = e1;
            }
            if (lane == 0){
                float ri = __fdividef(1.0f, sv);
                sm->rinv[g] = ri;
                float yt = sm->Ys[g][t];
                sm->yup[g] = fmaf(dv, ri, fmaf(sm->wfc[128], yt, bfc0));
            }
        }
        __syncthreads();
        // ======== phase 4: LSTM cell (accurate activations) ========
        if (tid < 256){
            int g = tid >> 7, i = tid & 127;
            float yu = sm->yup[g];
            float gi = sm->gatesH[g][i]        + yu*sm->wih[i]        + sm->bsum[i];
            float gf = sm->gatesH[g][NH+i]     + yu*sm->wih[NH+i]     + sm->bsum[NH+i];
            float gg = sm->gatesH[g][2*NH+i]   + yu*sm->wih[2*NH+i]   + sm->bsum[2*NH+i];
            float go = sm->gatesH[g][3*NH+i]   + yu*sm->wih[3*NH+i]   + sm->bsum[3*NH+i];
            float co = sm->hc[NH+i][g];
            float cn = fsig(gf)*co + fsig(gi)*ftanh(gg);
            float hn = fsig(go)*ftanh(cn);
            sm->hc[i][g]       = hn;
            sm->hc[NH+i][g]    = cn;
            sm->hc16x[g][i]    = __float2half(hn);
            sm->hc16x[g][NH+i] = __float2half(cn);
        }
        __syncthreads();
    }

    // ---- final context from last step's be/rinv (X from global) ----
    {
        int g = tid >> 8, half = (tid >> 7) & 1, i = tid & 127;
        int t0 = half ? 32 : 0;
        int t1 = half ? TM1 : 32;
        const float* Xg = X + (b0+g)*TM1*NI;
        float acc = 0.0f;
        for (int tt = t0; tt < t1; tt++)
            acc = fmaf(sm->be[g][tt], Xg[tt*NI + i], acc);
        sm->ctxpart[half][g][i] = acc;
    }
    __syncthreads();

    // ---- output: y[b] = bo + Wo[0:128].h + Wo[128:256].ctx  (warps 0 and 8) ----
    if (w == 0 || w == 8){
        int g = w >> 3;
        float ri = sm->rinv[g];
        float acc = 0.0f;
        #pragma unroll
        for (int r = 0; r < 4; r++){
            int i = lane*4 + r;
            float ctx = (sm->ctxpart[0][g][i] + sm->ctxpart[1][g][i]) * ri;
            acc += sm->wo[i]*sm->hc[i][g] + sm->wo[NI+i]*ctx;
        }
        acc = warp_sum(acc);
        if (lane == 0) out[b0 + g] = acc + bo[0];
    }
}

extern "C" void kernel_launch(void* const* d_in, const int* in_sizes, int n_in,
                              void* d_out, int out_size) {
    const float* X   = (const float*)d_in[0];
    const float* Y   = (const float*)d_in[1];
    const float* aW1 = (const float*)d_in[2];
    const float* ab1 = (const float*)d_in[3];
    const float* aW2 = (const float*)d_in[4];
    // d_in[5] = ab2: constant softmax shift, mathematically irrelevant
    const float* Wih = (const float*)d_in[6];
    const float* Whh = (const float*)d_in[7];
    const float* bih = (const float*)d_in[8];
    const float* bhh = (const float*)d_in[9];
    const float* Wfc = (const float*)d_in[10];
    const float* bfc = (const float*)d_in[11];
    const float* Wo  = (const float*)d_in[12];
    const float* bo  = (const float*)d_in[13];
    float* out = (float*)d_out;

    size_t p_smem = (size_t)(8192 + 128*129 + 128) * sizeof(float);
    size_t m_smem = sizeof(SmemMain);
    cudaFuncSetAttribute(p_kernel,    cudaFuncAttributeMaxDynamicSharedMemorySize, (int)p_smem);
    cudaFuncSetAttribute(main_kernel, cudaFuncAttributeMaxDynamicSharedMemorySize, (int)m_smem);

    prep_kernel<<<64, 256>>>(aW1, Whh);
    p_kernel<<<BATCH, 256, p_smem>>>(X, aW1, ab1);
    main_kernel<<<NCTA, NTHR, m_smem>>>(X, Y, aW2, Wih, bih, bhh, Wfc, bfc, Wo, bo, out);
}